// round 6
// baseline (speedup 1.0000x reference)
#include <cuda_runtime.h>
#include <cuda_bf16.h>
#include <cstdint>

#define N_NODES  50000
#define N_EDGES  800000
#define D_IN     128
#define D_HID    256
#define N_GRAPHS 256
#define SCAN_B   49   // ceil(50000/1024)

// ---------------- scratch (device globals; no runtime allocation) ----------------
__device__ float g_agg1[N_NODES * D_IN];
__device__ float g_h1  [N_NODES * D_HID];
__device__ float g_agg2[N_NODES * D_HID];
__device__ float g_h2  [N_NODES * D_HID];
__device__ int   g_cnt [N_NODES];
__device__ int   g_row [N_NODES + 1];
__device__ int   g_cur [N_NODES];
__device__ int   g_col [N_EDGES];
__device__ int   g_bagg[64];
__device__ int   g_bpref[64];
__device__ int   g_flag[64];
__device__ int   g_idx64;

// ---------------- helpers ----------------
__device__ __forceinline__ uint32_t smem_u32(const void* p) {
    uint32_t a;
    asm("{ .reg .u64 t; cvta.to.shared.u64 t, %1; cvt.u32.u64 %0, t; }" : "=r"(a) : "l"(p));
    return a;
}
__device__ __forceinline__ void ldsm_x4(uint32_t* r, uint32_t addr) {
    asm volatile("ldmatrix.sync.aligned.m8n8.x4.shared.b16 {%0,%1,%2,%3}, [%4];"
                 : "=r"(r[0]), "=r"(r[1]), "=r"(r[2]), "=r"(r[3]) : "r"(addr));
}
__device__ __forceinline__ void mma16816(float* c, const uint32_t* a, const uint32_t* b) {
    asm volatile(
        "mma.sync.aligned.m16n8k16.row.col.f32.bf16.bf16.f32 "
        "{%0,%1,%2,%3}, {%4,%5,%6,%7}, {%8,%9}, {%0,%1,%2,%3};"
        : "+f"(c[0]), "+f"(c[1]), "+f"(c[2]), "+f"(c[3])
        : "r"(a[0]), "r"(a[1]), "r"(a[2]), "r"(a[3]), "r"(b[0]), "r"(b[1]));
}
__device__ __forceinline__ unsigned short bf_bits(__nv_bfloat16 h) {
    return *(unsigned short*)&h;
}
// split fp32x4 -> bf16 hi quad + bf16 lo quad, store as ushort4
__device__ __forceinline__ void split4(float4 v, unsigned short* ph, unsigned short* pl) {
    __nv_bfloat16 hx = __float2bfloat16(v.x), hy = __float2bfloat16(v.y);
    __nv_bfloat16 hz = __float2bfloat16(v.z), hw = __float2bfloat16(v.w);
    __nv_bfloat16 lx = __float2bfloat16(v.x - __bfloat162float(hx));
    __nv_bfloat16 ly = __float2bfloat16(v.y - __bfloat162float(hy));
    __nv_bfloat16 lz = __float2bfloat16(v.z - __bfloat162float(hz));
    __nv_bfloat16 lw = __float2bfloat16(v.w - __bfloat162float(hw));
    *(ushort4*)ph = make_ushort4(bf_bits(hx), bf_bits(hy), bf_bits(hz), bf_bits(hw));
    *(ushort4*)pl = make_ushort4(bf_bits(lx), bf_bits(ly), bf_bits(lz), bf_bits(lw));
}

// ---------------- prep: dtype detect + zero histogram/flags ----------------
__global__ void prep_kernel(const int* __restrict__ ei) {
    int i = blockIdx.x * blockDim.x + threadIdx.x;
    if (i == 0) {
        int any = 0;
#pragma unroll
        for (int j = 1; j < 256; j += 2) any |= ei[j];
        g_idx64 = (any == 0) ? 1 : 0;
    }
    if (i < 64) g_flag[i] = 0;
    int stride = gridDim.x * blockDim.x;
    for (; i < N_NODES; i += stride) g_cnt[i] = 0;
}

__device__ __forceinline__ int load_idx_(const void* p, int i, int i64) {
    if (i64) return (int)((const long long*)p)[i];
    return ((const int*)p)[i];
}

// ---------------- CSR build ----------------
__global__ void hist_kernel(const void* __restrict__ ei) {
    int i64 = g_idx64;
    int i = blockIdx.x * blockDim.x + threadIdx.x;
    int stride = gridDim.x * blockDim.x;
    for (; i < N_EDGES; i += stride) {
        int d = load_idx_(ei, i + N_EDGES, i64);
        atomicAdd(&g_cnt[d], 1);
    }
}

// single-pass scan with decoupled lookback
__global__ void scan_kernel() {
    __shared__ int wsum[32];
    __shared__ int s_excl;
    int b = blockIdx.x, t = threadIdx.x;
    int i = b * 1024 + t;
    int v = (i < N_NODES) ? g_cnt[i] : 0;
    int lane = t & 31, w = t >> 5;
    int s = v;
#pragma unroll
    for (int o = 1; o < 32; o <<= 1) {
        int u = __shfl_up_sync(0xffffffffu, s, o);
        if (lane >= o) s += u;
    }
    if (lane == 31) wsum[w] = s;
    __syncthreads();
    if (w == 0) {
        int ws = wsum[lane];
#pragma unroll
        for (int o = 1; o < 32; o <<= 1) {
            int u = __shfl_up_sync(0xffffffffu, ws, o);
            if (lane >= o) ws += u;
        }
        wsum[lane] = ws;
    }
    __syncthreads();
    int incl = s + (w > 0 ? wsum[w - 1] : 0);
    if (t == 0) {
        int total = wsum[31];
        if (b == 0) {
            g_bpref[0] = total;
            __threadfence();
            *(volatile int*)&g_flag[0] = 2;
            s_excl = 0;
        } else {
            g_bagg[b] = total;
            __threadfence();
            *(volatile int*)&g_flag[b] = 1;
            int ex = 0, j = b - 1;
            while (true) {
                int f;
                do { f = *(volatile int*)&g_flag[j]; } while (f == 0);
                __threadfence();
                if (f == 2) { ex += *(volatile int*)&g_bpref[j]; break; }
                ex += *(volatile int*)&g_bagg[j];
                j--;
            }
            g_bpref[b] = ex + total;
            __threadfence();
            *(volatile int*)&g_flag[b] = 2;
            s_excl = ex;
        }
    }
    __syncthreads();
    int r = incl - v + s_excl;
    if (i < N_NODES) { g_row[i] = r; g_cur[i] = r; }
    if (i == N_NODES - 1) g_row[N_NODES] = N_EDGES;
}

__global__ void fill_kernel(const void* __restrict__ ei) {
    int i64 = g_idx64;
    int i = blockIdx.x * blockDim.x + threadIdx.x;
    int stride = gridDim.x * blockDim.x;
    for (; i < N_EDGES; i += stride) {
        int s = load_idx_(ei, i, i64);
        int d = load_idx_(ei, i + N_EDGES, i64);
        int pos = atomicAdd(&g_cur[d], 1);
        g_col[pos] = s;
    }
}

// ---------------- deterministic gather aggregation ----------------
template<int D>
__global__ void gather_agg(const float* __restrict__ x, float* __restrict__ agg) {
    int warp = (blockIdx.x * blockDim.x + threadIdx.x) >> 5;
    if (warp >= N_NODES) return;
    int lane = threadIdx.x & 31;
    int beg = g_row[warp], end = g_row[warp + 1];
    constexpr int V = D / 128;
    float4 a[V];
#pragma unroll
    for (int v = 0; v < V; v++) a[v] = make_float4(0.f, 0.f, 0.f, 0.f);
    int p = beg;
    for (; p + 2 <= end; p += 2) {
        int s0 = g_col[p], s1 = g_col[p + 1];
        const float4* x0 = (const float4*)x + (size_t)s0 * (D / 4);
        const float4* x1 = (const float4*)x + (size_t)s1 * (D / 4);
        float4 v0[V], v1[V];
#pragma unroll
        for (int v = 0; v < V; v++) { v0[v] = x0[lane + v * 32]; v1[v] = x1[lane + v * 32]; }
#pragma unroll
        for (int v = 0; v < V; v++) {
            a[v].x += v0[v].x + v1[v].x; a[v].y += v0[v].y + v1[v].y;
            a[v].z += v0[v].z + v1[v].z; a[v].w += v0[v].w + v1[v].w;
        }
    }
    if (p < end) {
        int s0 = g_col[p];
        const float4* x0 = (const float4*)x + (size_t)s0 * (D / 4);
#pragma unroll
        for (int v = 0; v < V; v++) {
            float4 v0 = x0[lane + v * 32];
            a[v].x += v0.x; a[v].y += v0.y; a[v].z += v0.z; a[v].w += v0.w;
        }
    }
    float4* ap = (float4*)agg + (size_t)warp * (D / 4);
#pragma unroll
    for (int v = 0; v < V; v++) ap[lane + v * 32] = a[v];
}

// ---------------- mma.sync bf16-split dual GEMM + bias + relu ----------------
// C[m,n] = relu( sum_ph A_ph[m,:] . W_ph[n,:] + bias[n] )
// BM=128, BN=128, BK=32; 8 warps (2M x 4N), warp tile 64x32.
// Split: v = hi + lo (bf16); product = AhiWhi + AhiWlo + AloWhi.
// smem rows padded to 40 bf16 (80B): ldmatrix conflict-free, 16B aligned.
template<int K, int PHASES>
__global__ __launch_bounds__(256) void gemm_mma(
    const float* __restrict__ A1, const float* __restrict__ W1,
    const float* __restrict__ A2, const float* __restrict__ W2,
    const float* __restrict__ bias, float* __restrict__ C) {
    __shared__ __align__(16) unsigned short sAh[128][40];
    __shared__ __align__(16) unsigned short sAl[128][40];
    __shared__ __align__(16) unsigned short sWh[128][40];
    __shared__ __align__(16) unsigned short sWl[128][40];

    const int tid = threadIdx.x, lane = tid & 31, wid = tid >> 5;
    const int wm = wid >> 2, wn = wid & 3;        // 2 x 4 warp grid
    const int bm = blockIdx.x * 128, bn = blockIdx.y * 128;

    float acc[4][4][4];
#pragma unroll
    for (int i = 0; i < 4; i++)
#pragma unroll
        for (int j = 0; j < 4; j++)
#pragma unroll
            for (int q = 0; q < 4; q++) acc[i][j][q] = 0.f;

    const uint32_t baseAh = smem_u32(sAh), baseAl = smem_u32(sAl);
    const uint32_t baseWh = smem_u32(sWh), baseWl = smem_u32(sWl);

    // ldmatrix per-lane byte offsets
    const uint32_t aoff = (uint32_t)((lane & 15) * 80 + (((lane >> 4) & 1) << 4));
    const uint32_t boff = (uint32_t)(((((lane >> 4) << 3) + (lane & 7)) * 80) + (((lane >> 3) & 1) << 4));
    const uint32_t awb = (uint32_t)(wm * 64 * 80);
    const uint32_t bwb = (uint32_t)(wn * 32 * 80);

    const float4 z4 = make_float4(0.f, 0.f, 0.f, 0.f);

#pragma unroll 1
    for (int ph = 0; ph < PHASES; ph++) {
        const float* A = ph ? A2 : A1;
        const float* W = ph ? W2 : W1;
#pragma unroll 1
        for (int c = 0; c < K / 32; c++) {
            const int kb = c * 32;
            __syncthreads();
#pragma unroll
            for (int it = 0; it < 4; it++) {
                int f = it * 256 + tid;
                int row = f >> 3, kq = f & 7;
                float4 va = z4;
                int gr = bm + row;
                if (gr < N_NODES)
                    va = *(const float4*)(A + (size_t)gr * K + kb + kq * 4);
                split4(va, &sAh[row][kq * 4], &sAl[row][kq * 4]);
                float4 vw = *(const float4*)(W + (size_t)(bn + row) * K + kb + kq * 4);
                split4(vw, &sWh[row][kq * 4], &sWl[row][kq * 4]);
            }
            __syncthreads();

#pragma unroll
            for (int k16 = 0; k16 < 2; k16++) {
                const uint32_t koff = (uint32_t)(k16 * 32);   // 16 bf16 = 32B
                uint32_t af[4][4], bh[4][2], bl[4][2], t[4];
                // B hi: two x4 loads cover ni pairs (0,1) and (2,3)
                ldsm_x4(t, baseWh + bwb + 0 * 1280 + koff + boff);
                bh[0][0] = t[0]; bh[0][1] = t[1]; bh[1][0] = t[2]; bh[1][1] = t[3];
                ldsm_x4(t, baseWh + bwb + 1 * 1280 + koff + boff);
                bh[2][0] = t[0]; bh[2][1] = t[1]; bh[3][0] = t[2]; bh[3][1] = t[3];
                // B lo
                ldsm_x4(t, baseWl + bwb + 0 * 1280 + koff + boff);
                bl[0][0] = t[0]; bl[0][1] = t[1]; bl[1][0] = t[2]; bl[1][1] = t[3];
                ldsm_x4(t, baseWl + bwb + 1 * 1280 + koff + boff);
                bl[2][0] = t[0]; bl[2][1] = t[1]; bl[3][0] = t[2]; bl[3][1] = t[3];
                // A hi
#pragma unroll
                for (int mi = 0; mi < 4; mi++)
                    ldsm_x4(af[mi], baseAh + awb + mi * 1280 + koff + aoff);
#pragma unroll
                for (int mi = 0; mi < 4; mi++)
#pragma unroll
                    for (int ni = 0; ni < 4; ni++) {
                        mma16816(acc[mi][ni], af[mi], bh[ni]);
                        mma16816(acc[mi][ni], af[mi], bl[ni]);
                    }
                // A lo (reuse regs)
#pragma unroll
                for (int mi = 0; mi < 4; mi++)
                    ldsm_x4(af[mi], baseAl + awb + mi * 1280 + koff + aoff);
#pragma unroll
                for (int mi = 0; mi < 4; mi++)
#pragma unroll
                    for (int ni = 0; ni < 4; ni++)
                        mma16816(acc[mi][ni], af[mi], bh[ni]);
            }
        }
    }

    // epilogue: bias + relu
    const int r0 = lane >> 2;
    const int cc = (lane & 3) * 2;
#pragma unroll
    for (int mi = 0; mi < 4; mi++) {
        int row0 = bm + wm * 64 + mi * 16 + r0;
        int row1 = row0 + 8;
#pragma unroll
        for (int ni = 0; ni < 4; ni++) {
            int col = bn + wn * 32 + ni * 8 + cc;
            float2 bb = *(const float2*)(bias + col);
            if (row0 < N_NODES) {
                float2 o;
                o.x = fmaxf(acc[mi][ni][0] + bb.x, 0.f);
                o.y = fmaxf(acc[mi][ni][1] + bb.y, 0.f);
                *(float2*)(C + (size_t)row0 * D_HID + col) = o;
            }
            if (row1 < N_NODES) {
                float2 o;
                o.x = fmaxf(acc[mi][ni][2] + bb.x, 0.f);
                o.y = fmaxf(acc[mi][ni][3] + bb.y, 0.f);
                *(float2*)(C + (size_t)row1 * D_HID + col) = o;
            }
        }
    }
}

// ---------------- fused mean-pool + FC + sigmoid (deterministic) ----------------
__global__ void poolfc_kernel(const float* __restrict__ h, const void* __restrict__ batch,
                              const float* __restrict__ Wfc, const float* __restrict__ bfc,
                              float* __restrict__ out) {
    int g = blockIdx.x;
    int t = threadIdx.x;
    int i64 = g_idx64;

    int start, end;
    {
        int lo = 0, hi = N_NODES;
        while (lo < hi) { int mid = (lo + hi) >> 1; if (load_idx_(batch, mid, i64) < g) lo = mid + 1; else hi = mid; }
        start = lo;
        lo = start; hi = N_NODES;
        while (lo < hi) { int mid = (lo + hi) >> 1; if (load_idx_(batch, mid, i64) < g + 1) lo = mid + 1; else hi = mid; }
        end = lo;
    }

    float s = 0.f;
    for (int n = start; n < end; n++)
        s += h[(size_t)n * D_HID + t];
    float inv = 1.0f / fmaxf((float)(end - start), 1.0f);
    float p = s * inv;

    __shared__ float r0[256], r1[256];
    r0[t] = p * Wfc[t];
    r1[t] = p * Wfc[D_HID + t];
    __syncthreads();
    for (int off = 128; off > 0; off >>= 1) {
        if (t < off) { r0[t] += r0[t + off]; r1[t] += r1[t + off]; }
        __syncthreads();
    }
    if (t == 0) {
        out[g * 2 + 0] = 1.0f / (1.0f + expf(-(r0[0] + bfc[0])));
        out[g * 2 + 1] = 1.0f / (1.0f + expf(-(r1[0] + bfc[1])));
    }
}

// ---------------- launch ----------------
extern "C" void kernel_launch(void* const* d_in, const int* in_sizes, int n_in,
                              void* d_out, int out_size) {
    const float* x  = (const float*)d_in[0];
    const void*  ei = d_in[1];
    const void*  bt = d_in[2];
    int wbase = (n_in >= 12 && in_sizes[3] == 1) ? 4 : 3;
    const float* W1_root = (const float*)d_in[wbase + 0];
    const float* W1_rel  = (const float*)d_in[wbase + 1];
    const float* b1      = (const float*)d_in[wbase + 2];
    const float* W2_root = (const float*)d_in[wbase + 3];
    const float* W2_rel  = (const float*)d_in[wbase + 4];
    const float* b2      = (const float*)d_in[wbase + 5];
    const float* Wfc     = (const float*)d_in[wbase + 6];
    const float* bfc     = (const float*)d_in[wbase + 7];
    float* out = (float*)d_out;

    dim3 ggrid((N_NODES + 127) / 128, 2);

    // (1) prep  (2) hist  (3) scan  (4) fill <- profiled slot
    prep_kernel<<<200, 256>>>((const int*)ei);
    hist_kernel<<<1024, 256>>>(ei);
    scan_kernel<<<SCAN_B, 1024>>>();
    fill_kernel<<<1024, 256>>>(ei);

    // (5) gather L1, (6) dual GEMM L1 -> h1
    gather_agg<D_IN><<<(N_NODES * 32 + 255) / 256, 256>>>(x, g_agg1);
    gemm_mma<D_IN, 2><<<ggrid, 256>>>(x, W1_root, g_agg1, W1_rel, b1, g_h1);

    // (7) gather L2, (8) dual GEMM L2 -> h2
    gather_agg<D_HID><<<(N_NODES * 32 + 255) / 256, 256>>>(g_h1, g_agg2);
    gemm_mma<D_HID, 2><<<ggrid, 256>>>(g_h1, W2_root, g_agg2, W2_rel, b2, g_h2);

    // (9) pool + FC + sigmoid
    poolfc_kernel<<<N_GRAPHS, 256>>>(g_h2, bt, Wfc, bfc, out);
    (void)out_size;
}

// round 7
// speedup vs baseline: 1.0734x; 1.0734x over previous
#include <cuda_runtime.h>
#include <cstdint>

#define N_NODES  50000
#define N_EDGES  800000
#define D_IN     128
#define D_HID    256
#define N_GRAPHS 256
#define SCAN_B   49   // ceil(50000/1024)

typedef unsigned long long ull;

// ---------------- scratch (device globals; no runtime allocation) ----------------
__device__ float g_agg1[N_NODES * D_IN];
__device__ float g_h1  [N_NODES * D_HID];
__device__ float g_agg2[N_NODES * D_HID];
__device__ float g_h2  [N_NODES * D_HID];
__device__ int   g_cnt [N_NODES];
__device__ int   g_row [N_NODES + 1];
__device__ int   g_cur [N_NODES];
__device__ int   g_col [N_EDGES];
__device__ int   g_bagg[64];
__device__ int   g_bpref[64];
__device__ int   g_flag[64];
__device__ int   g_bar;
__device__ int   g_idx64;

// ---------------- packed f32x2 helpers ----------------
__device__ __forceinline__ ull pack2(float lo, float hi) {
    ull r;
    asm("mov.b64 %0, {%1, %2};" : "=l"(r) : "f"(lo), "f"(hi));
    return r;
}
__device__ __forceinline__ void unpack2(ull v, float& lo, float& hi) {
    asm("mov.b64 {%0, %1}, %2;" : "=f"(lo), "=f"(hi) : "l"(v));
}
__device__ __forceinline__ ull fma2(ull a, ull b, ull c) {
    ull r;
    asm("fma.rn.f32x2 %0, %1, %2, %3;" : "=l"(r) : "l"(a), "l"(b), "l"(c));
    return r;
}

// ---------------- prep: dtype detect + zero histogram/flags ----------------
__global__ void prep_kernel(const int* __restrict__ ei) {
    int i = blockIdx.x * blockDim.x + threadIdx.x;
    if (i == 0) {
        int any = 0;
#pragma unroll
        for (int j = 1; j < 256; j += 2) any |= ei[j];
        g_idx64 = (any == 0) ? 1 : 0;
        g_bar = 0;
    }
    if (i < 64) g_flag[i] = 0;
    int stride = gridDim.x * blockDim.x;
    for (; i < N_NODES; i += stride) g_cnt[i] = 0;
}

__device__ __forceinline__ int load_idx_(const void* p, int i, int i64) {
    if (i64) return (int)((const long long*)p)[i];
    return ((const int*)p)[i];
}

// ---------------- CSR build ----------------
__global__ void hist_kernel(const void* __restrict__ ei) {
    int i64 = g_idx64;
    int i = blockIdx.x * blockDim.x + threadIdx.x;
    int stride = gridDim.x * blockDim.x;
    for (; i < N_EDGES; i += stride) {
        int d = load_idx_(ei, i + N_EDGES, i64);
        atomicAdd(&g_cnt[d], 1);
    }
}

// scan (decoupled lookback) + grid barrier + fill, one kernel (49 blocks, all resident)
__global__ void scanfill_kernel(const void* __restrict__ ei) {
    __shared__ int wsum[32];
    __shared__ int s_excl;
    int b = blockIdx.x, t = threadIdx.x;
    int i = b * 1024 + t;
    int v = (i < N_NODES) ? g_cnt[i] : 0;
    int lane = t & 31, w = t >> 5;
    int s = v;
#pragma unroll
    for (int o = 1; o < 32; o <<= 1) {
        int u = __shfl_up_sync(0xffffffffu, s, o);
        if (lane >= o) s += u;
    }
    if (lane == 31) wsum[w] = s;
    __syncthreads();
    if (w == 0) {
        int ws = wsum[lane];
#pragma unroll
        for (int o = 1; o < 32; o <<= 1) {
            int u = __shfl_up_sync(0xffffffffu, ws, o);
            if (lane >= o) ws += u;
        }
        wsum[lane] = ws;
    }
    __syncthreads();
    int incl = s + (w > 0 ? wsum[w - 1] : 0);
    if (t == 0) {
        int total = wsum[31];
        if (b == 0) {
            g_bpref[0] = total;
            __threadfence();
            *(volatile int*)&g_flag[0] = 2;
            s_excl = 0;
        } else {
            g_bagg[b] = total;
            __threadfence();
            *(volatile int*)&g_flag[b] = 1;
            int ex = 0, j = b - 1;
            while (true) {
                int f;
                do { f = *(volatile int*)&g_flag[j]; } while (f == 0);
                __threadfence();
                if (f == 2) { ex += *(volatile int*)&g_bpref[j]; break; }
                ex += *(volatile int*)&g_bagg[j];
                j--;
            }
            g_bpref[b] = ex + total;
            __threadfence();
            *(volatile int*)&g_flag[b] = 2;
            s_excl = ex;
        }
    }
    __syncthreads();
    int r = incl - v + s_excl;
    if (i < N_NODES) { g_row[i] = r; g_cur[i] = r; }
    if (i == N_NODES - 1) g_row[N_NODES] = N_EDGES;

    // grid barrier (all SCAN_B blocks are resident)
    __syncthreads();
    if (t == 0) {
        __threadfence();
        atomicAdd(&g_bar, 1);
        while (*(volatile int*)&g_bar < SCAN_B) {}
    }
    __syncthreads();

    // fill (edge grid-stride)
    int i64 = g_idx64;
    for (int e = b * 1024 + t; e < N_EDGES; e += SCAN_B * 1024) {
        int src = load_idx_(ei, e, i64);
        int dst = load_idx_(ei, e + N_EDGES, i64);
        int pos = atomicAdd(&g_cur[dst], 1);
        g_col[pos] = src;
    }
}

// ---------------- deterministic gather aggregation (batched-index, high MLP) ----------------
// One warp per destination node. U neighbor indices loaded at once by lanes and
// shfl-broadcast; U*V independent row loads in flight per iteration.
template<int D>
__global__ void gather_agg(const float* __restrict__ x, float* __restrict__ agg) {
    int warp = (blockIdx.x * blockDim.x + threadIdx.x) >> 5;
    if (warp >= N_NODES) return;
    int lane = threadIdx.x & 31;
    int beg = g_row[warp], end = g_row[warp + 1];
    constexpr int V = D / 128;            // float4s per lane per row
    constexpr int U = (V == 1) ? 8 : 4;   // neighbors per batch
    float4 a[V];
#pragma unroll
    for (int vv = 0; vv < V; vv++) a[vv] = make_float4(0.f, 0.f, 0.f, 0.f);

    int n = end - beg;
    int nfull = n & ~(U - 1);
    int p = beg;
    for (; p < beg + nfull; p += U) {
        int c = g_col[p + (lane & (U - 1))];
        float4 v[U][V];
#pragma unroll
        for (int j = 0; j < U; j++) {
            int s = __shfl_sync(0xffffffffu, c, j);
            const float4* xp = (const float4*)x + (size_t)s * (D / 4);
#pragma unroll
            for (int vv = 0; vv < V; vv++) v[j][vv] = xp[lane + vv * 32];
        }
#pragma unroll
        for (int j = 0; j < U; j++)
#pragma unroll
            for (int vv = 0; vv < V; vv++) {
                a[vv].x += v[j][vv].x; a[vv].y += v[j][vv].y;
                a[vv].z += v[j][vv].z; a[vv].w += v[j][vv].w;
            }
    }
    for (; p < end; p++) {
        int s = g_col[p];
        const float4* xp = (const float4*)x + (size_t)s * (D / 4);
#pragma unroll
        for (int vv = 0; vv < V; vv++) {
            float4 v0 = xp[lane + vv * 32];
            a[vv].x += v0.x; a[vv].y += v0.y; a[vv].z += v0.z; a[vv].w += v0.w;
        }
    }
    float4* ap = (float4*)agg + (size_t)warp * (D / 4);
#pragma unroll
    for (int vv = 0; vv < V; vv++) ap[lane + vv * 32] = a[vv];
}

// ---------------- GEMM: C = relu(A1@W1^T + A2@W2^T + bias)  (f32x2 packed FMA) ----------------
#define PADW 132
template<int K, int PHASES, bool LOAD_C, bool HAS_BIAS, bool RELU>
__global__ __launch_bounds__(256) void gemm_phase(
    const float* __restrict__ A1, const float* __restrict__ W1,
    const float* __restrict__ A2, const float* __restrict__ W2,
    const float* __restrict__ bias, float* __restrict__ C) {
    constexpr int BK = 16;
    constexpr int T = K / BK;
    __shared__ float As[2][BK][PADW];
    __shared__ float Bs[2][BK][PADW];

    int tid = threadIdx.x;
    int tx = tid & 15;
    int ty = tid >> 4;
    int bm = blockIdx.x * 128;
    int bn = blockIdx.y * 128;

    int lm = tid >> 2;
    int lk = (tid & 3) * 4;

    ull acc[8][4];
#pragma unroll
    for (int i = 0; i < 8; i++)
#pragma unroll
        for (int j = 0; j < 4; j++) acc[i][j] = pack2(0.f, 0.f);

    const float4 z4 = make_float4(0.f, 0.f, 0.f, 0.f);

#pragma unroll 1
    for (int phase = 0; phase < PHASES; phase++) {
        const float* A = phase ? A2 : A1;
        const float* W = phase ? W2 : W1;

        float4 ra0, ra1, rb0, rb1;
        {
            int r0 = bm + lm, r1 = bm + lm + 64;
            ra0 = (r0 < N_NODES) ? *(const float4*)(A + (size_t)r0 * K + lk) : z4;
            ra1 = (r1 < N_NODES) ? *(const float4*)(A + (size_t)r1 * K + lk) : z4;
            rb0 = *(const float4*)(W + (size_t)(bn + lm) * K + lk);
            rb1 = *(const float4*)(W + (size_t)(bn + lm + 64) * K + lk);
            As[0][lk + 0][lm] = ra0.x; As[0][lk + 1][lm] = ra0.y;
            As[0][lk + 2][lm] = ra0.z; As[0][lk + 3][lm] = ra0.w;
            As[0][lk + 0][lm + 64] = ra1.x; As[0][lk + 1][lm + 64] = ra1.y;
            As[0][lk + 2][lm + 64] = ra1.z; As[0][lk + 3][lm + 64] = ra1.w;
            Bs[0][lk + 0][lm] = rb0.x; Bs[0][lk + 1][lm] = rb0.y;
            Bs[0][lk + 2][lm] = rb0.z; Bs[0][lk + 3][lm] = rb0.w;
            Bs[0][lk + 0][lm + 64] = rb1.x; Bs[0][lk + 1][lm + 64] = rb1.y;
            Bs[0][lk + 2][lm + 64] = rb1.z; Bs[0][lk + 3][lm + 64] = rb1.w;
        }
        __syncthreads();

#pragma unroll 1
        for (int t = 0; t < T; t++) {
            int cur = t & 1, nxt = cur ^ 1;
            if (t + 1 < T) {
                int k0 = (t + 1) * BK;
                int r0 = bm + lm, r1 = bm + lm + 64;
                ra0 = (r0 < N_NODES) ? *(const float4*)(A + (size_t)r0 * K + k0 + lk) : z4;
                ra1 = (r1 < N_NODES) ? *(const float4*)(A + (size_t)r1 * K + k0 + lk) : z4;
                rb0 = *(const float4*)(W + (size_t)(bn + lm) * K + k0 + lk);
                rb1 = *(const float4*)(W + (size_t)(bn + lm + 64) * K + k0 + lk);
            }
#pragma unroll
            for (int k = 0; k < BK; k++) {
                float4 av0 = *(const float4*)&As[cur][k][ty * 8];
                float4 av1 = *(const float4*)&As[cur][k][ty * 8 + 4];
                float4 bv0 = *(const float4*)&Bs[cur][k][tx * 4];
                float4 bv1 = *(const float4*)&Bs[cur][k][64 + tx * 4];
                ull b0 = pack2(bv0.x, bv0.y);
                ull b1 = pack2(bv0.z, bv0.w);
                ull b2 = pack2(bv1.x, bv1.y);
                ull b3 = pack2(bv1.z, bv1.w);
                ull ad;
                ad = pack2(av0.x, av0.x);
                acc[0][0] = fma2(ad, b0, acc[0][0]); acc[0][1] = fma2(ad, b1, acc[0][1]);
                acc[0][2] = fma2(ad, b2, acc[0][2]); acc[0][3] = fma2(ad, b3, acc[0][3]);
                ad = pack2(av0.y, av0.y);
                acc[1][0] = fma2(ad, b0, acc[1][0]); acc[1][1] = fma2(ad, b1, acc[1][1]);
                acc[1][2] = fma2(ad, b2, acc[1][2]); acc[1][3] = fma2(ad, b3, acc[1][3]);
                ad = pack2(av0.z, av0.z);
                acc[2][0] = fma2(ad, b0, acc[2][0]); acc[2][1] = fma2(ad, b1, acc[2][1]);
                acc[2][2] = fma2(ad, b2, acc[2][2]); acc[2][3] = fma2(ad, b3, acc[2][3]);
                ad = pack2(av0.w, av0.w);
                acc[3][0] = fma2(ad, b0, acc[3][0]); acc[3][1] = fma2(ad, b1, acc[3][1]);
                acc[3][2] = fma2(ad, b2, acc[3][2]); acc[3][3] = fma2(ad, b3, acc[3][3]);
                ad = pack2(av1.x, av1.x);
                acc[4][0] = fma2(ad, b0, acc[4][0]); acc[4][1] = fma2(ad, b1, acc[4][1]);
                acc[4][2] = fma2(ad, b2, acc[4][2]); acc[4][3] = fma2(ad, b3, acc[4][3]);
                ad = pack2(av1.y, av1.y);
                acc[5][0] = fma2(ad, b0, acc[5][0]); acc[5][1] = fma2(ad, b1, acc[5][1]);
                acc[5][2] = fma2(ad, b2, acc[5][2]); acc[5][3] = fma2(ad, b3, acc[5][3]);
                ad = pack2(av1.z, av1.z);
                acc[6][0] = fma2(ad, b0, acc[6][0]); acc[6][1] = fma2(ad, b1, acc[6][1]);
                acc[6][2] = fma2(ad, b2, acc[6][2]); acc[6][3] = fma2(ad, b3, acc[6][3]);
                ad = pack2(av1.w, av1.w);
                acc[7][0] = fma2(ad, b0, acc[7][0]); acc[7][1] = fma2(ad, b1, acc[7][1]);
                acc[7][2] = fma2(ad, b2, acc[7][2]); acc[7][3] = fma2(ad, b3, acc[7][3]);
            }
            if (t + 1 < T) {
                As[nxt][lk + 0][lm] = ra0.x; As[nxt][lk + 1][lm] = ra0.y;
                As[nxt][lk + 2][lm] = ra0.z; As[nxt][lk + 3][lm] = ra0.w;
                As[nxt][lk + 0][lm + 64] = ra1.x; As[nxt][lk + 1][lm + 64] = ra1.y;
                As[nxt][lk + 2][lm + 64] = ra1.z; As[nxt][lk + 3][lm + 64] = ra1.w;
                Bs[nxt][lk + 0][lm] = rb0.x; Bs[nxt][lk + 1][lm] = rb0.y;
                Bs[nxt][lk + 2][lm] = rb0.z; Bs[nxt][lk + 3][lm] = rb0.w;
                Bs[nxt][lk + 0][lm + 64] = rb1.x; Bs[nxt][lk + 1][lm + 64] = rb1.y;
                Bs[nxt][lk + 2][lm + 64] = rb1.z; Bs[nxt][lk + 3][lm + 64] = rb1.w;
            }
            __syncthreads();
        }
        __syncthreads();
    }

    float4 bb0 = make_float4(0.f, 0.f, 0.f, 0.f), bb1 = bb0;
    if (HAS_BIAS) {
        bb0 = *(const float4*)(bias + bn + tx * 4);
        bb1 = *(const float4*)(bias + bn + 64 + tx * 4);
    }
#pragma unroll
    for (int i = 0; i < 8; i++) {
        int row = bm + ty * 8 + i;
        if (row < N_NODES) {
            float* cp0 = C + (size_t)row * D_HID + bn + tx * 4;
            float* cp1 = cp0 + 64;
            float c0, c1, c2, c3, c4, c5, c6, c7;
            unpack2(acc[i][0], c0, c1);
            unpack2(acc[i][1], c2, c3);
            unpack2(acc[i][2], c4, c5);
            unpack2(acc[i][3], c6, c7);
            float4 o0 = make_float4(c0 + bb0.x, c1 + bb0.y, c2 + bb0.z, c3 + bb0.w);
            float4 o1 = make_float4(c4 + bb1.x, c5 + bb1.y, c6 + bb1.z, c7 + bb1.w);
            if (LOAD_C) {
                float4 p0 = *(const float4*)cp0;
                float4 p1 = *(const float4*)cp1;
                o0.x += p0.x; o0.y += p0.y; o0.z += p0.z; o0.w += p0.w;
                o1.x += p1.x; o1.y += p1.y; o1.z += p1.z; o1.w += p1.w;
            }
            if (RELU) {
                o0.x = fmaxf(o0.x, 0.f); o0.y = fmaxf(o0.y, 0.f);
                o0.z = fmaxf(o0.z, 0.f); o0.w = fmaxf(o0.w, 0.f);
                o1.x = fmaxf(o1.x, 0.f); o1.y = fmaxf(o1.y, 0.f);
                o1.z = fmaxf(o1.z, 0.f); o1.w = fmaxf(o1.w, 0.f);
            }
            *(float4*)cp0 = o0;
            *(float4*)cp1 = o1;
        }
    }
}

// ---------------- fused mean-pool + FC + sigmoid (deterministic) ----------------
__global__ void poolfc_kernel(const float* __restrict__ h, const void* __restrict__ batch,
                              const float* __restrict__ Wfc, const float* __restrict__ bfc,
                              float* __restrict__ out) {
    int g = blockIdx.x;
    int t = threadIdx.x;
    int i64 = g_idx64;

    int start, end;
    {
        int lo = 0, hi = N_NODES;
        while (lo < hi) { int mid = (lo + hi) >> 1; if (load_idx_(batch, mid, i64) < g) lo = mid + 1; else hi = mid; }
        start = lo;
        lo = start; hi = N_NODES;
        while (lo < hi) { int mid = (lo + hi) >> 1; if (load_idx_(batch, mid, i64) < g + 1) lo = mid + 1; else hi = mid; }
        end = lo;
    }

    float s = 0.f;
    for (int n = start; n < end; n++)
        s += h[(size_t)n * D_HID + t];
    float inv = 1.0f / fmaxf((float)(end - start), 1.0f);
    float p = s * inv;

    __shared__ float r0[256], r1[256];
    r0[t] = p * Wfc[t];
    r1[t] = p * Wfc[D_HID + t];
    __syncthreads();
    for (int off = 128; off > 0; off >>= 1) {
        if (t < off) { r0[t] += r0[t + off]; r1[t] += r1[t + off]; }
        __syncthreads();
    }
    if (t == 0) {
        out[g * 2 + 0] = 1.0f / (1.0f + expf(-(r0[0] + bfc[0])));
        out[g * 2 + 1] = 1.0f / (1.0f + expf(-(r1[0] + bfc[1])));
    }
}

// ---------------- launch ----------------
extern "C" void kernel_launch(void* const* d_in, const int* in_sizes, int n_in,
                              void* d_out, int out_size) {
    const float* x  = (const float*)d_in[0];
    const void*  ei = d_in[1];
    const void*  bt = d_in[2];
    int wbase = (n_in >= 12 && in_sizes[3] == 1) ? 4 : 3;
    const float* W1_root = (const float*)d_in[wbase + 0];
    const float* W1_rel  = (const float*)d_in[wbase + 1];
    const float* b1      = (const float*)d_in[wbase + 2];
    const float* W2_root = (const float*)d_in[wbase + 3];
    const float* W2_rel  = (const float*)d_in[wbase + 4];
    const float* b2      = (const float*)d_in[wbase + 5];
    const float* Wfc     = (const float*)d_in[wbase + 6];
    const float* bfc     = (const float*)d_in[wbase + 7];
    float* out = (float*)d_out;

    dim3 ggrid((N_NODES + 127) / 128, 2);

    // (1) prep  (2) hist  (3) scan+fill  (4) gather1 <- profiled slot
    prep_kernel<<<200, 256>>>((const int*)ei);
    hist_kernel<<<1024, 256>>>(ei);
    scanfill_kernel<<<SCAN_B, 1024>>>(ei);
    gather_agg<D_IN><<<(N_NODES * 32 + 255) / 256, 256>>>(x, g_agg1);

    // (5) dual GEMM L1 -> h1
    gemm_phase<D_IN, 2, false, true, true><<<ggrid, 256>>>(
        x, W1_root, g_agg1, W1_rel, b1, g_h1);

    // (6) gather L2, (7) dual GEMM L2 -> h2
    gather_agg<D_HID><<<(N_NODES * 32 + 255) / 256, 256>>>(g_h1, g_agg2);
    gemm_phase<D_HID, 2, false, true, true><<<ggrid, 256>>>(
        g_h1, W2_root, g_agg2, W2_rel, b2, g_h2);

    // (8) pool + FC + sigmoid
    poolfc_kernel<<<N_GRAPHS, 256>>>(g_h2, bt, Wfc, bfc, out);
    (void)out_size;
}

// round 8
// speedup vs baseline: 9.9570x; 9.2764x over previous
#include <cuda_runtime.h>
#include <cstdint>

#define N_NODES  50000
#define N_EDGES  800000
#define D_IN     128
#define D_HID    256
#define N_GRAPHS 256
#define NB       148
#define NT       256

typedef unsigned long long ull;

// ---------------- scratch (device globals; no runtime allocation) ----------------
__device__ float g_agg1[N_NODES * D_IN];
__device__ float g_h1  [N_NODES * D_HID];
__device__ float g_agg2[N_NODES * D_HID];
__device__ float g_h2  [N_NODES * D_HID];
__device__ int   g_cnt [N_NODES];
__device__ int   g_row [N_NODES + 1];
__device__ int   g_cur [N_NODES];
__device__ int   g_col [N_EDGES];
__device__ int   g_bagg[NB];
__device__ int   g_bpref[NB];
__device__ int   g_barrier_ctr;
__device__ int   g_idx64;

// ---------------- packed f32x2 helpers ----------------
__device__ __forceinline__ ull pack2(float lo, float hi) {
    ull r;
    asm("mov.b64 %0, {%1, %2};" : "=l"(r) : "f"(lo), "f"(hi));
    return r;
}
__device__ __forceinline__ void unpack2(ull v, float& lo, float& hi) {
    asm("mov.b64 {%0, %1}, %2;" : "=f"(lo), "=f"(hi) : "l"(v));
}
__device__ __forceinline__ ull fma2(ull a, ull b, ull c) {
    ull r;
    asm("fma.rn.f32x2 %0, %1, %2, %3;" : "=l"(r) : "l"(a), "l"(b), "l"(c));
    return r;
}

__device__ __forceinline__ int load_idx_(const void* p, int i, int i64) {
    if (i64) return (int)((const long long*)p)[i];
    return ((const int*)p)[i];
}

// ---------------- shared memory union ----------------
struct SmemGemm { float As[2][16][132]; float Bs[2][16][132]; };   // 33792 B
struct SmemScan { int wsum[32]; };
struct SmemPool { float r0[NT]; float r1[NT]; };
union SmemAll { SmemGemm g; SmemScan s; SmemPool p; };

// ---------------- grid barrier (all NB blocks resident by construction) ----------
__device__ __forceinline__ void gridbar(int target) {
    __syncthreads();
    if (threadIdx.x == 0) {
        __threadfence();
        atomicAdd(&g_barrier_ctr, 1);
        while (*(volatile int*)&g_barrier_ctr < target) { }
    }
    __syncthreads();
}

__global__ void reset_kernel() { g_barrier_ctr = 0; }

// ---------------- block-wide exclusive scan over 256 thread values ----------------
__device__ int block_scan_excl(int v, SmemScan& ss, int& total) {
    int lane = threadIdx.x & 31, w = threadIdx.x >> 5;
    int s = v;
#pragma unroll
    for (int o = 1; o < 32; o <<= 1) {
        int u = __shfl_up_sync(0xffffffffu, s, o);
        if (lane >= o) s += u;
    }
    if (lane == 31) ss.wsum[w] = s;
    __syncthreads();
    if (w == 0) {
        int ws = (lane < 8) ? ss.wsum[lane] : 0;
#pragma unroll
        for (int o = 1; o < 8; o <<= 1) {
            int u = __shfl_up_sync(0xffffffffu, ws, o);
            if (lane >= o) ws += u;
        }
        if (lane < 8) ss.wsum[lane] = ws;
    }
    __syncthreads();
    int incl = s + (w > 0 ? ss.wsum[w - 1] : 0);
    total = ss.wsum[7];
    return incl - v;
}

// ---------------- gather stage: agg[n] = sum_{s in nbrs(n)} x[s] ------------------
template<int D>
__device__ void gather_stage(const float* __restrict__ x, float* __restrict__ agg) {
    int lane = threadIdx.x & 31;
    int gw = blockIdx.x * (NT / 32) + (threadIdx.x >> 5);
    constexpr int V = D / 128;
    for (int node = gw; node < N_NODES; node += NB * (NT / 32)) {
        int beg = g_row[node], end = g_row[node + 1];
        float4 a[V];
#pragma unroll
        for (int v = 0; v < V; v++) a[v] = make_float4(0.f, 0.f, 0.f, 0.f);
        int p = beg;
        for (; p + 2 <= end; p += 2) {
            int s0 = g_col[p], s1 = g_col[p + 1];
            const float4* x0 = (const float4*)x + (size_t)s0 * (D / 4);
            const float4* x1 = (const float4*)x + (size_t)s1 * (D / 4);
            float4 v0[V], v1[V];
#pragma unroll
            for (int v = 0; v < V; v++) { v0[v] = x0[lane + v * 32]; v1[v] = x1[lane + v * 32]; }
#pragma unroll
            for (int v = 0; v < V; v++) {
                a[v].x += v0[v].x + v1[v].x; a[v].y += v0[v].y + v1[v].y;
                a[v].z += v0[v].z + v1[v].z; a[v].w += v0[v].w + v1[v].w;
            }
        }
        if (p < end) {
            int s0 = g_col[p];
            const float4* x0 = (const float4*)x + (size_t)s0 * (D / 4);
#pragma unroll
            for (int v = 0; v < V; v++) {
                float4 v0 = x0[lane + v * 32];
                a[v].x += v0.x; a[v].y += v0.y; a[v].z += v0.z; a[v].w += v0.w;
            }
        }
        float4* ap = (float4*)agg + (size_t)node * (D / 4);
#pragma unroll
        for (int v = 0; v < V; v++) ap[lane + v * 32] = a[v];
    }
}

// ---------------- gemm stage: C = relu(A1@W1^T + A2@W2^T + bias) ------------------
// 128x128 tiles, BK=16, f32x2 packed FMA, tile-loop grid-strided over NB blocks.
#define N_MTILES ((N_NODES + 127) / 128)
template<int K>
__device__ void gemm_stage(const float* __restrict__ A1, const float* __restrict__ W1,
                           const float* __restrict__ A2, const float* __restrict__ W2,
                           const float* __restrict__ bias, float* __restrict__ C,
                           SmemGemm& sm) {
    constexpr int BK = 16;
    constexpr int T = K / BK;
    int tid = threadIdx.x;
    int tx = tid & 15;
    int ty = tid >> 4;
    int lm = tid >> 2;
    int lk = (tid & 3) * 4;
    const float4 z4 = make_float4(0.f, 0.f, 0.f, 0.f);

    for (int tile = blockIdx.x; tile < N_MTILES * 2; tile += NB) {
        int bm = (tile >> 1) * 128;
        int bn = (tile & 1) * 128;

        ull acc[8][4];
#pragma unroll
        for (int i = 0; i < 8; i++)
#pragma unroll
            for (int j = 0; j < 4; j++) acc[i][j] = pack2(0.f, 0.f);

#pragma unroll 1
        for (int phase = 0; phase < 2; phase++) {
            const float* A = phase ? A2 : A1;
            const float* W = phase ? W2 : W1;

            float4 ra0, ra1, rb0, rb1;
            {
                int r0 = bm + lm, r1 = bm + lm + 64;
                ra0 = (r0 < N_NODES) ? *(const float4*)(A + (size_t)r0 * K + lk) : z4;
                ra1 = (r1 < N_NODES) ? *(const float4*)(A + (size_t)r1 * K + lk) : z4;
                rb0 = *(const float4*)(W + (size_t)(bn + lm) * K + lk);
                rb1 = *(const float4*)(W + (size_t)(bn + lm + 64) * K + lk);
                sm.As[0][lk + 0][lm] = ra0.x; sm.As[0][lk + 1][lm] = ra0.y;
                sm.As[0][lk + 2][lm] = ra0.z; sm.As[0][lk + 3][lm] = ra0.w;
                sm.As[0][lk + 0][lm + 64] = ra1.x; sm.As[0][lk + 1][lm + 64] = ra1.y;
                sm.As[0][lk + 2][lm + 64] = ra1.z; sm.As[0][lk + 3][lm + 64] = ra1.w;
                sm.Bs[0][lk + 0][lm] = rb0.x; sm.Bs[0][lk + 1][lm] = rb0.y;
                sm.Bs[0][lk + 2][lm] = rb0.z; sm.Bs[0][lk + 3][lm] = rb0.w;
                sm.Bs[0][lk + 0][lm + 64] = rb1.x; sm.Bs[0][lk + 1][lm + 64] = rb1.y;
                sm.Bs[0][lk + 2][lm + 64] = rb1.z; sm.Bs[0][lk + 3][lm + 64] = rb1.w;
            }
            __syncthreads();

#pragma unroll 1
            for (int t = 0; t < T; t++) {
                int cur = t & 1, nxt = cur ^ 1;
                if (t + 1 < T) {
                    int k0 = (t + 1) * BK;
                    int r0 = bm + lm, r1 = bm + lm + 64;
                    ra0 = (r0 < N_NODES) ? *(const float4*)(A + (size_t)r0 * K + k0 + lk) : z4;
                    ra1 = (r1 < N_NODES) ? *(const float4*)(A + (size_t)r1 * K + k0 + lk) : z4;
                    rb0 = *(const float4*)(W + (size_t)(bn + lm) * K + k0 + lk);
                    rb1 = *(const float4*)(W + (size_t)(bn + lm + 64) * K + k0 + lk);
                }
#pragma unroll
                for (int k = 0; k < BK; k++) {
                    float4 av0 = *(const float4*)&sm.As[cur][k][ty * 8];
                    float4 av1 = *(const float4*)&sm.As[cur][k][ty * 8 + 4];
                    float4 bv0 = *(const float4*)&sm.Bs[cur][k][tx * 4];
                    float4 bv1 = *(const float4*)&sm.Bs[cur][k][64 + tx * 4];
                    ull b0 = pack2(bv0.x, bv0.y);
                    ull b1 = pack2(bv0.z, bv0.w);
                    ull b2 = pack2(bv1.x, bv1.y);
                    ull b3 = pack2(bv1.z, bv1.w);
                    ull ad;
                    ad = pack2(av0.x, av0.x);
                    acc[0][0] = fma2(ad, b0, acc[0][0]); acc[0][1] = fma2(ad, b1, acc[0][1]);
                    acc[0][2] = fma2(ad, b2, acc[0][2]); acc[0][3] = fma2(ad, b3, acc[0][3]);
                    ad = pack2(av0.y, av0.y);
                    acc[1][0] = fma2(ad, b0, acc[1][0]); acc[1][1] = fma2(ad, b1, acc[1][1]);
                    acc[1][2] = fma2(ad, b2, acc[1][2]); acc[1][3] = fma2(ad, b3, acc[1][3]);
                    ad = pack2(av0.z, av0.z);
                    acc[2][0] = fma2(ad, b0, acc[2][0]); acc[2][1] = fma2(ad, b1, acc[2][1]);
                    acc[2][2] = fma2(ad, b2, acc[2][2]); acc[2][3] = fma2(ad, b3, acc[2][3]);
                    ad = pack2(av0.w, av0.w);
                    acc[3][0] = fma2(ad, b0, acc[3][0]); acc[3][1] = fma2(ad, b1, acc[3][1]);
                    acc[3][2] = fma2(ad, b2, acc[3][2]); acc[3][3] = fma2(ad, b3, acc[3][3]);
                    ad = pack2(av1.x, av1.x);
                    acc[4][0] = fma2(ad, b0, acc[4][0]); acc[4][1] = fma2(ad, b1, acc[4][1]);
                    acc[4][2] = fma2(ad, b2, acc[4][2]); acc[4][3] = fma2(ad, b3, acc[4][3]);
                    ad = pack2(av1.y, av1.y);
                    acc[5][0] = fma2(ad, b0, acc[5][0]); acc[5][1] = fma2(ad, b1, acc[5][1]);
                    acc[5][2] = fma2(ad, b2, acc[5][2]); acc[5][3] = fma2(ad, b3, acc[5][3]);
                    ad = pack2(av1.z, av1.z);
                    acc[6][0] = fma2(ad, b0, acc[6][0]); acc[6][1] = fma2(ad, b1, acc[6][1]);
                    acc[6][2] = fma2(ad, b2, acc[6][2]); acc[6][3] = fma2(ad, b3, acc[6][3]);
                    ad = pack2(av1.w, av1.w);
                    acc[7][0] = fma2(ad, b0, acc[7][0]); acc[7][1] = fma2(ad, b1, acc[7][1]);
                    acc[7][2] = fma2(ad, b2, acc[7][2]); acc[7][3] = fma2(ad, b3, acc[7][3]);
                }
                if (t + 1 < T) {
                    sm.As[nxt][lk + 0][lm] = ra0.x; sm.As[nxt][lk + 1][lm] = ra0.y;
                    sm.As[nxt][lk + 2][lm] = ra0.z; sm.As[nxt][lk + 3][lm] = ra0.w;
                    sm.As[nxt][lk + 0][lm + 64] = ra1.x; sm.As[nxt][lk + 1][lm + 64] = ra1.y;
                    sm.As[nxt][lk + 2][lm + 64] = ra1.z; sm.As[nxt][lk + 3][lm + 64] = ra1.w;
                    sm.Bs[nxt][lk + 0][lm] = rb0.x; sm.Bs[nxt][lk + 1][lm] = rb0.y;
                    sm.Bs[nxt][lk + 2][lm] = rb0.z; sm.Bs[nxt][lk + 3][lm] = rb0.w;
                    sm.Bs[nxt][lk + 0][lm + 64] = rb1.x; sm.Bs[nxt][lk + 1][lm + 64] = rb1.y;
                    sm.Bs[nxt][lk + 2][lm + 64] = rb1.z; sm.Bs[nxt][lk + 3][lm + 64] = rb1.w;
                }
                __syncthreads();
            }
            __syncthreads();
        }

        // epilogue: bias + relu
        float4 bb0 = *(const float4*)(bias + bn + tx * 4);
        float4 bb1 = *(const float4*)(bias + bn + 64 + tx * 4);
#pragma unroll
        for (int i = 0; i < 8; i++) {
            int row = bm + ty * 8 + i;
            if (row < N_NODES) {
                float c0, c1, c2, c3, c4, c5, c6, c7;
                unpack2(acc[i][0], c0, c1);
                unpack2(acc[i][1], c2, c3);
                unpack2(acc[i][2], c4, c5);
                unpack2(acc[i][3], c6, c7);
                float4 o0 = make_float4(fmaxf(c0 + bb0.x, 0.f), fmaxf(c1 + bb0.y, 0.f),
                                        fmaxf(c2 + bb0.z, 0.f), fmaxf(c3 + bb0.w, 0.f));
                float4 o1 = make_float4(fmaxf(c4 + bb1.x, 0.f), fmaxf(c5 + bb1.y, 0.f),
                                        fmaxf(c6 + bb1.z, 0.f), fmaxf(c7 + bb1.w, 0.f));
                float* cp = C + (size_t)row * D_HID + bn + tx * 4;
                *(float4*)cp = o0;
                *(float4*)(cp + 64) = o1;
            }
        }
    }
}

// ---------------- the mega kernel ----------------
__global__ __launch_bounds__(NT) void mega_kernel(
    const float* __restrict__ x, const void* __restrict__ ei, const void* __restrict__ bt,
    const float* __restrict__ W1_root, const float* __restrict__ W1_rel, const float* __restrict__ b1,
    const float* __restrict__ W2_root, const float* __restrict__ W2_rel, const float* __restrict__ b2,
    const float* __restrict__ Wfc, const float* __restrict__ bfc, float* __restrict__ out) {
    __shared__ SmemAll sm;
    const int b = blockIdx.x, t = threadIdx.x;
    int epoch = 0;

    // A: dtype detect + zero histogram
    if (b == 0 && t == 0) {
        const int* e32 = (const int*)ei;
        int any = 0;
#pragma unroll
        for (int j = 1; j < 256; j += 2) any |= e32[j];
        g_idx64 = (any == 0) ? 1 : 0;
    }
    for (int i = b * NT + t; i < N_NODES; i += NB * NT) g_cnt[i] = 0;
    gridbar(++epoch * NB);

    const int i64 = g_idx64;

    // B: histogram of in-degrees
    for (int i = b * NT + t; i < N_EDGES; i += NB * NT) {
        int d = load_idx_(ei, i + N_EDGES, i64);
        atomicAdd(&g_cnt[d], 1);
    }
    gridbar(++epoch * NB);

    // C: exclusive scan -> g_row / g_cur
    {
        const int CHUNK = (N_NODES + NB - 1) / NB;   // 338
        int base = b * CHUNK;
        int lim = base + CHUNK; if (lim > N_NODES) lim = N_NODES;
        int i0 = base + t * 2, i1 = i0 + 1;
        int v0 = (i0 < lim) ? g_cnt[i0] : 0;
        int v1 = (i1 < lim) ? g_cnt[i1] : 0;
        int total;
        int ex = block_scan_excl(v0 + v1, sm.s, total);
        if (t == 0) g_bagg[b] = total;
        gridbar(++epoch * NB);
        if (b == 0) {
            int bv = (t < NB) ? g_bagg[t] : 0;
            int btot;
            int bex = block_scan_excl(bv, sm.s, btot);
            if (t < NB) g_bpref[t] = bex;
        }
        gridbar(++epoch * NB);
        int off = g_bpref[b];
        if (i0 < lim) { int r = off + ex;      g_row[i0] = r; g_cur[i0] = r; }
        if (i1 < lim) { int r = off + ex + v0; g_row[i1] = r; g_cur[i1] = r; }
        if (b == 0 && t == 0) g_row[N_NODES] = N_EDGES;
    }
    gridbar(++epoch * NB);

    // D: CSR fill
    for (int i = b * NT + t; i < N_EDGES; i += NB * NT) {
        int s = load_idx_(ei, i, i64);
        int d = load_idx_(ei, i + N_EDGES, i64);
        g_col[atomicAdd(&g_cur[d], 1)] = s;
    }
    gridbar(++epoch * NB);

    // E: gather layer 1
    gather_stage<D_IN>(x, g_agg1);
    gridbar(++epoch * NB);

    // F: dual GEMM layer 1
    gemm_stage<D_IN>(x, W1_root, g_agg1, W1_rel, b1, g_h1, sm.g);
    gridbar(++epoch * NB);

    // G: gather layer 2
    gather_stage<D_HID>(g_h1, g_agg2);
    gridbar(++epoch * NB);

    // H: dual GEMM layer 2
    gemm_stage<D_HID>(g_h1, W2_root, g_agg2, W2_rel, b2, g_h2, sm.g);
    gridbar(++epoch * NB);

    // I: mean-pool + FC + sigmoid (batch sorted -> contiguous segments)
    for (int g = b; g < N_GRAPHS; g += NB) {
        __syncthreads();
        int start, end;
        {
            int lo = 0, hi = N_NODES;
            while (lo < hi) { int mid = (lo + hi) >> 1; if (load_idx_(bt, mid, i64) < g) lo = mid + 1; else hi = mid; }
            start = lo;
            lo = start; hi = N_NODES;
            while (lo < hi) { int mid = (lo + hi) >> 1; if (load_idx_(bt, mid, i64) < g + 1) lo = mid + 1; else hi = mid; }
            end = lo;
        }
        float s = 0.f;
        for (int n = start; n < end; n++)
            s += g_h2[(size_t)n * D_HID + t];
        float p = s / fmaxf((float)(end - start), 1.0f);
        sm.p.r0[t] = p * Wfc[t];
        sm.p.r1[t] = p * Wfc[D_HID + t];
        __syncthreads();
        for (int off = 128; off > 0; off >>= 1) {
            if (t < off) { sm.p.r0[t] += sm.p.r0[t + off]; sm.p.r1[t] += sm.p.r1[t + off]; }
            __syncthreads();
        }
        if (t == 0) {
            out[g * 2 + 0] = 1.0f / (1.0f + expf(-(sm.p.r0[0] + bfc[0])));
            out[g * 2 + 1] = 1.0f / (1.0f + expf(-(sm.p.r1[0] + bfc[1])));
        }
    }
}

// ---------------- launch ----------------
extern "C" void kernel_launch(void* const* d_in, const int* in_sizes, int n_in,
                              void* d_out, int out_size) {
    const float* x  = (const float*)d_in[0];
    const void*  ei = d_in[1];
    const void*  bt = d_in[2];
    int wbase = (n_in >= 12 && in_sizes[3] == 1) ? 4 : 3;
    const float* W1_root = (const float*)d_in[wbase + 0];
    const float* W1_rel  = (const float*)d_in[wbase + 1];
    const float* b1      = (const float*)d_in[wbase + 2];
    const float* W2_root = (const float*)d_in[wbase + 3];
    const float* W2_rel  = (const float*)d_in[wbase + 4];
    const float* b2      = (const float*)d_in[wbase + 5];
    const float* Wfc     = (const float*)d_in[wbase + 6];
    const float* bfc     = (const float*)d_in[wbase + 7];
    float* out = (float*)d_out;

    reset_kernel<<<1, 1>>>();
    mega_kernel<<<NB, NT>>>(x, ei, bt, W1_root, W1_rel, b1,
                            W2_root, W2_rel, b2, Wfc, bfc, out);
    (void)out_size;
}

// round 9
// speedup vs baseline: 12.0806x; 1.2133x over previous
#include <cuda_runtime.h>
#include <cstdint>

#define N_NODES  50000
#define N_EDGES  800000
#define D_IN     128
#define D_HID    256
#define N_GRAPHS 256
#define NT       256

typedef unsigned long long ull;

// ---------------- scratch (device globals; no runtime allocation) ----------------
__device__ float g_agg1[N_NODES * D_IN];
__device__ float g_h1  [N_NODES * D_HID];
__device__ float g_agg2[N_NODES * D_HID];
__device__ float g_h2  [N_NODES * D_HID];
__device__ int   g_cnt [N_NODES];
__device__ int   g_row [N_NODES + 1];
__device__ int   g_cur [N_NODES];
__device__ int   g_col [N_EDGES];
__device__ int   g_bagg[512];
__device__ int   g_bpref[512];
__device__ int   g_barrier_ctr;
__device__ int   g_idx64;

// ---------------- packed f32x2 helpers ----------------
__device__ __forceinline__ ull pack2(float lo, float hi) {
    ull r;
    asm("mov.b64 %0, {%1, %2};" : "=l"(r) : "f"(lo), "f"(hi));
    return r;
}
__device__ __forceinline__ void unpack2(ull v, float& lo, float& hi) {
    asm("mov.b64 {%0, %1}, %2;" : "=f"(lo), "=f"(hi) : "l"(v));
}
__device__ __forceinline__ ull fma2(ull a, ull b, ull c) {
    ull r;
    asm("fma.rn.f32x2 %0, %1, %2, %3;" : "=l"(r) : "l"(a), "l"(b), "l"(c));
    return r;
}

__device__ __forceinline__ int load_idx_(const void* p, int i, int i64) {
    if (i64) return (int)((const long long*)p)[i];
    return ((const int*)p)[i];
}

// ---------------- shared memory union ----------------
struct SmemGemm { float As[2][16][132]; float Bs[2][16][132]; };   // 33792 B
struct SmemScan { int wsum[32]; };
struct SmemPool { float r0[NT]; float r1[NT]; };
union SmemAll { SmemGemm g; SmemScan s; SmemPool p; };

// ---------------- grid barrier (all gridDim.x blocks resident) --------------------
__device__ __forceinline__ void gridbar(int target) {
    __syncthreads();
    if (threadIdx.x == 0) {
        __threadfence();
        atomicAdd(&g_barrier_ctr, 1);
        while (*(volatile int*)&g_barrier_ctr < target) { }
    }
    __syncthreads();
}

__global__ void reset_kernel() { g_barrier_ctr = 0; }

// ---------------- block-wide exclusive scan over 256 thread values ----------------
__device__ int block_scan_excl(int v, SmemScan& ss, int& total) {
    int lane = threadIdx.x & 31, w = threadIdx.x >> 5;
    int s = v;
#pragma unroll
    for (int o = 1; o < 32; o <<= 1) {
        int u = __shfl_up_sync(0xffffffffu, s, o);
        if (lane >= o) s += u;
    }
    if (lane == 31) ss.wsum[w] = s;
    __syncthreads();
    if (w == 0) {
        int ws = (lane < 8) ? ss.wsum[lane] : 0;
#pragma unroll
        for (int o = 1; o < 8; o <<= 1) {
            int u = __shfl_up_sync(0xffffffffu, ws, o);
            if (lane >= o) ws += u;
        }
        if (lane < 8) ss.wsum[lane] = ws;
    }
    __syncthreads();
    int incl = s + (w > 0 ? ss.wsum[w - 1] : 0);
    total = ss.wsum[7];
    return incl - v;
}

// ---------------- gather stage: agg[n] = sum_{s in nbrs(n)} x[s] ------------------
template<int D>
__device__ void gather_stage(const float* __restrict__ x, float* __restrict__ agg) {
    int nb = gridDim.x;
    int lane = threadIdx.x & 31;
    int gw = blockIdx.x * (NT / 32) + (threadIdx.x >> 5);
    constexpr int V = D / 128;
    for (int node = gw; node < N_NODES; node += nb * (NT / 32)) {
        int beg = g_row[node], end = g_row[node + 1];
        float4 a[V];
#pragma unroll
        for (int v = 0; v < V; v++) a[v] = make_float4(0.f, 0.f, 0.f, 0.f);
        int p = beg;
        for (; p + 4 <= end; p += 4) {
            int s0 = g_col[p], s1 = g_col[p + 1], s2 = g_col[p + 2], s3 = g_col[p + 3];
            const float4* x0 = (const float4*)x + (size_t)s0 * (D / 4);
            const float4* x1 = (const float4*)x + (size_t)s1 * (D / 4);
            const float4* x2 = (const float4*)x + (size_t)s2 * (D / 4);
            const float4* x3 = (const float4*)x + (size_t)s3 * (D / 4);
#pragma unroll
            for (int v = 0; v < V; v++) {
                float4 v0 = x0[lane + v * 32];
                float4 v1 = x1[lane + v * 32];
                float4 v2 = x2[lane + v * 32];
                float4 v3 = x3[lane + v * 32];
                a[v].x += (v0.x + v1.x) + (v2.x + v3.x);
                a[v].y += (v0.y + v1.y) + (v2.y + v3.y);
                a[v].z += (v0.z + v1.z) + (v2.z + v3.z);
                a[v].w += (v0.w + v1.w) + (v2.w + v3.w);
            }
        }
        for (; p < end; p++) {
            int s0 = g_col[p];
            const float4* x0 = (const float4*)x + (size_t)s0 * (D / 4);
#pragma unroll
            for (int v = 0; v < V; v++) {
                float4 v0 = x0[lane + v * 32];
                a[v].x += v0.x; a[v].y += v0.y; a[v].z += v0.z; a[v].w += v0.w;
            }
        }
        float4* ap = (float4*)agg + (size_t)node * (D / 4);
#pragma unroll
        for (int v = 0; v < V; v++) ap[lane + v * 32] = a[v];
    }
}

// ---------------- gemm stage: C = relu(A1@W1^T + A2@W2^T + bias) ------------------
#define N_MTILES ((N_NODES + 127) / 128)
template<int K>
__device__ void gemm_stage(const float* __restrict__ A1, const float* __restrict__ W1,
                           const float* __restrict__ A2, const float* __restrict__ W2,
                           const float* __restrict__ bias, float* __restrict__ C,
                           SmemGemm& sm) {
    constexpr int BK = 16;
    constexpr int T = K / BK;
    int nb = gridDim.x;
    int tid = threadIdx.x;
    int tx = tid & 15;
    int ty = tid >> 4;
    int lm = tid >> 2;
    int lk = (tid & 3) * 4;
    const float4 z4 = make_float4(0.f, 0.f, 0.f, 0.f);

    for (int tile = blockIdx.x; tile < N_MTILES * 2; tile += nb) {
        int bm = (tile >> 1) * 128;
        int bn = (tile & 1) * 128;

        ull acc[8][4];
#pragma unroll
        for (int i = 0; i < 8; i++)
#pragma unroll
            for (int j = 0; j < 4; j++) acc[i][j] = pack2(0.f, 0.f);

#pragma unroll 1
        for (int phase = 0; phase < 2; phase++) {
            const float* A = phase ? A2 : A1;
            const float* W = phase ? W2 : W1;

            float4 ra0, ra1, rb0, rb1;
            {
                int r0 = bm + lm, r1 = bm + lm + 64;
                ra0 = (r0 < N_NODES) ? *(const float4*)(A + (size_t)r0 * K + lk) : z4;
                ra1 = (r1 < N_NODES) ? *(const float4*)(A + (size_t)r1 * K + lk) : z4;
                rb0 = *(const float4*)(W + (size_t)(bn + lm) * K + lk);
                rb1 = *(const float4*)(W + (size_t)(bn + lm + 64) * K + lk);
                sm.As[0][lk + 0][lm] = ra0.x; sm.As[0][lk + 1][lm] = ra0.y;
                sm.As[0][lk + 2][lm] = ra0.z; sm.As[0][lk + 3][lm] = ra0.w;
                sm.As[0][lk + 0][lm + 64] = ra1.x; sm.As[0][lk + 1][lm + 64] = ra1.y;
                sm.As[0][lk + 2][lm + 64] = ra1.z; sm.As[0][lk + 3][lm + 64] = ra1.w;
                sm.Bs[0][lk + 0][lm] = rb0.x; sm.Bs[0][lk + 1][lm] = rb0.y;
                sm.Bs[0][lk + 2][lm] = rb0.z; sm.Bs[0][lk + 3][lm] = rb0.w;
                sm.Bs[0][lk + 0][lm + 64] = rb1.x; sm.Bs[0][lk + 1][lm + 64] = rb1.y;
                sm.Bs[0][lk + 2][lm + 64] = rb1.z; sm.Bs[0][lk + 3][lm + 64] = rb1.w;
            }
            __syncthreads();

#pragma unroll 1
            for (int t = 0; t < T; t++) {
                int cur = t & 1, nxt = cur ^ 1;
                if (t + 1 < T) {
                    int k0 = (t + 1) * BK;
                    int r0 = bm + lm, r1 = bm + lm + 64;
                    ra0 = (r0 < N_NODES) ? *(const float4*)(A + (size_t)r0 * K + k0 + lk) : z4;
                    ra1 = (r1 < N_NODES) ? *(const float4*)(A + (size_t)r1 * K + k0 + lk) : z4;
                    rb0 = *(const float4*)(W + (size_t)(bn + lm) * K + k0 + lk);
                    rb1 = *(const float4*)(W + (size_t)(bn + lm + 64) * K + k0 + lk);
                }
#pragma unroll
                for (int k = 0; k < BK; k++) {
                    float4 av0 = *(const float4*)&sm.As[cur][k][ty * 8];
                    float4 av1 = *(const float4*)&sm.As[cur][k][ty * 8 + 4];
                    float4 bv0 = *(const float4*)&sm.Bs[cur][k][tx * 4];
                    float4 bv1 = *(const float4*)&sm.Bs[cur][k][64 + tx * 4];
                    ull b0 = pack2(bv0.x, bv0.y);
                    ull b1 = pack2(bv0.z, bv0.w);
                    ull b2 = pack2(bv1.x, bv1.y);
                    ull b3 = pack2(bv1.z, bv1.w);
                    ull ad;
                    ad = pack2(av0.x, av0.x);
                    acc[0][0] = fma2(ad, b0, acc[0][0]); acc[0][1] = fma2(ad, b1, acc[0][1]);
                    acc[0][2] = fma2(ad, b2, acc[0][2]); acc[0][3] = fma2(ad, b3, acc[0][3]);
                    ad = pack2(av0.y, av0.y);
                    acc[1][0] = fma2(ad, b0, acc[1][0]); acc[1][1] = fma2(ad, b1, acc[1][1]);
                    acc[1][2] = fma2(ad, b2, acc[1][2]); acc[1][3] = fma2(ad, b3, acc[1][3]);
                    ad = pack2(av0.z, av0.z);
                    acc[2][0] = fma2(ad, b0, acc[2][0]); acc[2][1] = fma2(ad, b1, acc[2][1]);
                    acc[2][2] = fma2(ad, b2, acc[2][2]); acc[2][3] = fma2(ad, b3, acc[2][3]);
                    ad = pack2(av0.w, av0.w);
                    acc[3][0] = fma2(ad, b0, acc[3][0]); acc[3][1] = fma2(ad, b1, acc[3][1]);
                    acc[3][2] = fma2(ad, b2, acc[3][2]); acc[3][3] = fma2(ad, b3, acc[3][3]);
                    ad = pack2(av1.x, av1.x);
                    acc[4][0] = fma2(ad, b0, acc[4][0]); acc[4][1] = fma2(ad, b1, acc[4][1]);
                    acc[4][2] = fma2(ad, b2, acc[4][2]); acc[4][3] = fma2(ad, b3, acc[4][3]);
                    ad = pack2(av1.y, av1.y);
                    acc[5][0] = fma2(ad, b0, acc[5][0]); acc[5][1] = fma2(ad, b1, acc[5][1]);
                    acc[5][2] = fma2(ad, b2, acc[5][2]); acc[5][3] = fma2(ad, b3, acc[5][3]);
                    ad = pack2(av1.z, av1.z);
                    acc[6][0] = fma2(ad, b0, acc[6][0]); acc[6][1] = fma2(ad, b1, acc[6][1]);
                    acc[6][2] = fma2(ad, b2, acc[6][2]); acc[6][3] = fma2(ad, b3, acc[6][3]);
                    ad = pack2(av1.w, av1.w);
                    acc[7][0] = fma2(ad, b0, acc[7][0]); acc[7][1] = fma2(ad, b1, acc[7][1]);
                    acc[7][2] = fma2(ad, b2, acc[7][2]); acc[7][3] = fma2(ad, b3, acc[7][3]);
                }
                if (t + 1 < T) {
                    sm.As[nxt][lk + 0][lm] = ra0.x; sm.As[nxt][lk + 1][lm] = ra0.y;
                    sm.As[nxt][lk + 2][lm] = ra0.z; sm.As[nxt][lk + 3][lm] = ra0.w;
                    sm.As[nxt][lk + 0][lm + 64] = ra1.x; sm.As[nxt][lk + 1][lm + 64] = ra1.y;
                    sm.As[nxt][lk + 2][lm + 64] = ra1.z; sm.As[nxt][lk + 3][lm + 64] = ra1.w;
                    sm.Bs[nxt][lk + 0][lm] = rb0.x; sm.Bs[nxt][lk + 1][lm] = rb0.y;
                    sm.Bs[nxt][lk + 2][lm] = rb0.z; sm.Bs[nxt][lk + 3][lm] = rb0.w;
                    sm.Bs[nxt][lk + 0][lm + 64] = rb1.x; sm.Bs[nxt][lk + 1][lm + 64] = rb1.y;
                    sm.Bs[nxt][lk + 2][lm + 64] = rb1.z; sm.Bs[nxt][lk + 3][lm + 64] = rb1.w;
                }
                __syncthreads();
            }
            __syncthreads();
        }

        // epilogue: bias + relu
        float4 bb0 = *(const float4*)(bias + bn + tx * 4);
        float4 bb1 = *(const float4*)(bias + bn + 64 + tx * 4);
#pragma unroll
        for (int i = 0; i < 8; i++) {
            int row = bm + ty * 8 + i;
            if (row < N_NODES) {
                float c0, c1, c2, c3, c4, c5, c6, c7;
                unpack2(acc[i][0], c0, c1);
                unpack2(acc[i][1], c2, c3);
                unpack2(acc[i][2], c4, c5);
                unpack2(acc[i][3], c6, c7);
                float4 o0 = make_float4(fmaxf(c0 + bb0.x, 0.f), fmaxf(c1 + bb0.y, 0.f),
                                        fmaxf(c2 + bb0.z, 0.f), fmaxf(c3 + bb0.w, 0.f));
                float4 o1 = make_float4(fmaxf(c4 + bb1.x, 0.f), fmaxf(c5 + bb1.y, 0.f),
                                        fmaxf(c6 + bb1.z, 0.f), fmaxf(c7 + bb1.w, 0.f));
                float* cp = C + (size_t)row * D_HID + bn + tx * 4;
                *(float4*)cp = o0;
                *(float4*)(cp + 64) = o1;
            }
        }
    }
}

// ---------------- the mega kernel ----------------
__global__ __launch_bounds__(NT, 2) void mega_kernel(
    const float* __restrict__ x, const void* __restrict__ ei, const void* __restrict__ bt,
    const float* __restrict__ W1_root, const float* __restrict__ W1_rel, const float* __restrict__ b1,
    const float* __restrict__ W2_root, const float* __restrict__ W2_rel, const float* __restrict__ b2,
    const float* __restrict__ Wfc, const float* __restrict__ bfc, float* __restrict__ out) {
    __shared__ SmemAll sm;
    const int b = blockIdx.x, t = threadIdx.x;
    const int nb = gridDim.x;
    int epoch = 0;

    // A: dtype detect + zero histogram
    if (b == 0 && t == 0) {
        const int* e32 = (const int*)ei;
        int any = 0;
#pragma unroll
        for (int j = 1; j < 256; j += 2) any |= e32[j];
        g_idx64 = (any == 0) ? 1 : 0;
    }
    for (int i = b * NT + t; i < N_NODES; i += nb * NT) g_cnt[i] = 0;
    gridbar(++epoch * nb);

    const int i64 = g_idx64;

    // B: histogram of in-degrees
    for (int i = b * NT + t; i < N_EDGES; i += nb * NT) {
        int d = load_idx_(ei, i + N_EDGES, i64);
        atomicAdd(&g_cnt[d], 1);
    }
    gridbar(++epoch * nb);

    // C: exclusive scan -> g_row / g_cur
    {
        const int CHUNK = (N_NODES + nb - 1) / nb;
        int base = b * CHUNK;
        int lim = base + CHUNK; if (lim > N_NODES) lim = N_NODES;
        int i0 = base + t * 2, i1 = i0 + 1;
        int v0 = (i0 < lim) ? g_cnt[i0] : 0;
        int v1 = (i1 < lim) ? g_cnt[i1] : 0;
        int total;
        int ex = block_scan_excl(v0 + v1, sm.s, total);
        if (t == 0) g_bagg[b] = total;
        gridbar(++epoch * nb);
        if (b == 0) {
            int j0 = t * 2, j1 = j0 + 1;
            int w0 = (j0 < nb) ? g_bagg[j0] : 0;
            int w1 = (j1 < nb) ? g_bagg[j1] : 0;
            int btot;
            int bex = block_scan_excl(w0 + w1, sm.s, btot);
            if (j0 < nb) g_bpref[j0] = bex;
            if (j1 < nb) g_bpref[j1] = bex + w0;
        }
        gridbar(++epoch * nb);
        int off = g_bpref[b];
        if (i0 < lim) { int r = off + ex;      g_row[i0] = r; g_cur[i0] = r; }
        if (i1 < lim) { int r = off + ex + v0; g_row[i1] = r; g_cur[i1] = r; }
        if (b == 0 && t == 0) g_row[N_NODES] = N_EDGES;
    }
    gridbar(++epoch * nb);

    // D: CSR fill
    for (int i = b * NT + t; i < N_EDGES; i += nb * NT) {
        int s = load_idx_(ei, i, i64);
        int d = load_idx_(ei, i + N_EDGES, i64);
        g_col[atomicAdd(&g_cur[d], 1)] = s;
    }
    gridbar(++epoch * nb);

    // E: gather layer 1
    gather_stage<D_IN>(x, g_agg1);
    gridbar(++epoch * nb);

    // F: dual GEMM layer 1
    gemm_stage<D_IN>(x, W1_root, g_agg1, W1_rel, b1, g_h1, sm.g);
    gridbar(++epoch * nb);

    // G: gather layer 2
    gather_stage<D_HID>(g_h1, g_agg2);
    gridbar(++epoch * nb);

    // H: dual GEMM layer 2
    gemm_stage<D_HID>(g_h1, W2_root, g_agg2, W2_rel, b2, g_h2, sm.g);
    gridbar(++epoch * nb);

    // I: mean-pool + FC + sigmoid (batch sorted -> contiguous segments)
    for (int g = b; g < N_GRAPHS; g += nb) {
        __syncthreads();
        int start, end;
        {
            int lo = 0, hi = N_NODES;
            while (lo < hi) { int mid = (lo + hi) >> 1; if (load_idx_(bt, mid, i64) < g) lo = mid + 1; else hi = mid; }
            start = lo;
            lo = start; hi = N_NODES;
            while (lo < hi) { int mid = (lo + hi) >> 1; if (load_idx_(bt, mid, i64) < g + 1) lo = mid + 1; else hi = mid; }
            end = lo;
        }
        float s = 0.f;
        for (int n = start; n < end; n++)
            s += g_h2[(size_t)n * D_HID + t];
        float p = s / fmaxf((float)(end - start), 1.0f);
        sm.p.r0[t] = p * Wfc[t];
        sm.p.r1[t] = p * Wfc[D_HID + t];
        __syncthreads();
        for (int off = 128; off > 0; off >>= 1) {
            if (t < off) { sm.p.r0[t] += sm.p.r0[t + off]; sm.p.r1[t] += sm.p.r1[t + off]; }
            __syncthreads();
        }
        if (t == 0) {
            out[g * 2 + 0] = 1.0f / (1.0f + expf(-(sm.p.r0[0] + bfc[0])));
            out[g * 2 + 1] = 1.0f / (1.0f + expf(-(sm.p.r1[0] + bfc[1])));
        }
    }
}

// ---------------- launch ----------------
extern "C" void kernel_launch(void* const* d_in, const int* in_sizes, int n_in,
                              void* d_out, int out_size) {
    const float* x  = (const float*)d_in[0];
    const void*  ei = d_in[1];
    const void*  bt = d_in[2];
    int wbase = (n_in >= 12 && in_sizes[3] == 1) ? 4 : 3;
    const float* W1_root = (const float*)d_in[wbase + 0];
    const float* W1_rel  = (const float*)d_in[wbase + 1];
    const float* b1      = (const float*)d_in[wbase + 2];
    const float* W2_root = (const float*)d_in[wbase + 3];
    const float* W2_rel  = (const float*)d_in[wbase + 4];
    const float* b2      = (const float*)d_in[wbase + 5];
    const float* Wfc     = (const float*)d_in[wbase + 6];
    const float* bfc     = (const float*)d_in[wbase + 7];
    float* out = (float*)d_out;

    // residency-safe grid sizing (deterministic host query; no allocation)
    int occ = 1;
    cudaOccupancyMaxActiveBlocksPerMultiprocessor(&occ, mega_kernel, NT, 0);
    if (occ < 1) occ = 1;
    if (occ > 2) occ = 2;
    int nb = 148 * occ;

    reset_kernel<<<1, 1>>>();
    mega_kernel<<<nb, NT>>>(x, ei, bt, W1_root, W1_rel, b1,
                            W2_root, W2_rel, b2, Wfc, bfc, out);
    (void)out_size;
}

// round 10
// speedup vs baseline: 12.8659x; 1.0650x over previous
#include <cuda_runtime.h>
#include <cstdint>

#define N_NODES  50000
#define N_EDGES  800000
#define D_IN     128
#define D_HID    256
#define N_GRAPHS 256
#define NT       256

typedef unsigned long long ull;

// ---------------- scratch (device globals; no runtime allocation) ----------------
__device__ float g_agg1[N_NODES * D_IN];
__device__ float g_h1  [N_NODES * D_HID];
__device__ float g_agg2[N_NODES * D_HID];
__device__ float g_h2  [N_NODES * D_HID];
__device__ int   g_cnt [N_NODES];
__device__ int   g_row [N_NODES + 1];
__device__ int   g_cur [N_NODES];
__device__ int   g_col [N_EDGES];
__device__ int   g_bagg[512];
__device__ int   g_bpref[512];
__device__ int   g_barrier_ctr;
__device__ int   g_wq[2];
__device__ int   g_idx64;

// ---------------- packed f32x2 helpers ----------------
__device__ __forceinline__ ull pack2(float lo, float hi) {
    ull r;
    asm("mov.b64 %0, {%1, %2};" : "=l"(r) : "f"(lo), "f"(hi));
    return r;
}
__device__ __forceinline__ void unpack2(ull v, float& lo, float& hi) {
    asm("mov.b64 {%0, %1}, %2;" : "=f"(lo), "=f"(hi) : "l"(v));
}
__device__ __forceinline__ ull fma2(ull a, ull b, ull c) {
    ull r;
    asm("fma.rn.f32x2 %0, %1, %2, %3;" : "=l"(r) : "l"(a), "l"(b), "l"(c));
    return r;
}

__device__ __forceinline__ int load_idx_(const void* p, int i, int i64) {
    if (i64) return (int)((const long long*)p)[i];
    return ((const int*)p)[i];
}

// ---------------- shared memory union ----------------
struct SmemGemm { float As[2][16][132]; float Bs[2][16][132]; int tile; };
struct SmemScan { int wsum[32]; };
struct SmemPool { float r0[NT]; float r1[NT]; };
union SmemAll { SmemGemm g; SmemScan s; SmemPool p; };

// ---------------- grid barrier (all gridDim.x blocks resident) --------------------
__device__ __forceinline__ void gridbar(int target) {
    __syncthreads();
    if (threadIdx.x == 0) {
        __threadfence();
        atomicAdd(&g_barrier_ctr, 1);
        while (*(volatile int*)&g_barrier_ctr < target) { __nanosleep(64); }
    }
    __syncthreads();
}

// ---------------- prep kernel: counters, histogram zero, dtype detect -------------
__global__ void reset_kernel(const int* __restrict__ ei) {
    int i = blockIdx.x * blockDim.x + threadIdx.x;
    if (i == 0) {
        g_barrier_ctr = 0;
        g_wq[0] = 0;
        g_wq[1] = 0;
        int any = 0;
#pragma unroll
        for (int j = 1; j < 256; j += 2) any |= ei[j];
        g_idx64 = (any == 0) ? 1 : 0;
    }
    for (; i < N_NODES; i += gridDim.x * blockDim.x) g_cnt[i] = 0;
}

// ---------------- block-wide exclusive scan over 256 thread values ----------------
__device__ int block_scan_excl(int v, SmemScan& ss, int& total) {
    int lane = threadIdx.x & 31, w = threadIdx.x >> 5;
    int s = v;
#pragma unroll
    for (int o = 1; o < 32; o <<= 1) {
        int u = __shfl_up_sync(0xffffffffu, s, o);
        if (lane >= o) s += u;
    }
    if (lane == 31) ss.wsum[w] = s;
    __syncthreads();
    if (w == 0) {
        int ws = (lane < 8) ? ss.wsum[lane] : 0;
#pragma unroll
        for (int o = 1; o < 8; o <<= 1) {
            int u = __shfl_up_sync(0xffffffffu, ws, o);
            if (lane >= o) ws += u;
        }
        if (lane < 8) ss.wsum[lane] = ws;
    }
    __syncthreads();
    int incl = s + (w > 0 ? ss.wsum[w - 1] : 0);
    total = ss.wsum[7];
    return incl - v;
}

// ---------------- gather stage (software-pipelined index prefetch) ----------------
template<int D>
__device__ void gather_stage(const float* __restrict__ x, float* __restrict__ agg) {
    constexpr int V = D / 128;
    int lane = threadIdx.x & 31;
    int gw = blockIdx.x * (NT / 32) + (threadIdx.x >> 5);
    int nw = gridDim.x * (NT / 32);
    for (int node = gw; node < N_NODES; node += nw) {
        int beg = g_row[node], end = g_row[node + 1];
        float4 a[V];
#pragma unroll
        for (int v = 0; v < V; v++) a[v] = make_float4(0.f, 0.f, 0.f, 0.f);

        int p = beg;
        int c0 = 0, c1 = 0, c2 = 0, c3 = 0;
        if (p + 4 <= end) {
            c0 = g_col[p]; c1 = g_col[p + 1]; c2 = g_col[p + 2]; c3 = g_col[p + 3];
        }
        while (p + 4 <= end) {
            int n0 = c0, n1 = c1, n2 = c2, n3 = c3;
            int pn = p + 4;
            if (pn + 4 <= end) {   // prefetch next batch's indices
                c0 = g_col[pn]; c1 = g_col[pn + 1]; c2 = g_col[pn + 2]; c3 = g_col[pn + 3];
            }
            const float4* x0 = (const float4*)x + (size_t)n0 * (D / 4);
            const float4* x1 = (const float4*)x + (size_t)n1 * (D / 4);
            const float4* x2 = (const float4*)x + (size_t)n2 * (D / 4);
            const float4* x3 = (const float4*)x + (size_t)n3 * (D / 4);
#pragma unroll
            for (int v = 0; v < V; v++) {
                float4 v0 = x0[lane + v * 32];
                float4 v1 = x1[lane + v * 32];
                float4 v2 = x2[lane + v * 32];
                float4 v3 = x3[lane + v * 32];
                a[v].x += (v0.x + v1.x) + (v2.x + v3.x);
                a[v].y += (v0.y + v1.y) + (v2.y + v3.y);
                a[v].z += (v0.z + v1.z) + (v2.z + v3.z);
                a[v].w += (v0.w + v1.w) + (v2.w + v3.w);
            }
            p = pn;
        }
        for (; p < end; p++) {
            int s0 = g_col[p];
            const float4* x0 = (const float4*)x + (size_t)s0 * (D / 4);
#pragma unroll
            for (int v = 0; v < V; v++) {
                float4 v0 = x0[lane + v * 32];
                a[v].x += v0.x; a[v].y += v0.y; a[v].z += v0.z; a[v].w += v0.w;
            }
        }
        float4* ap = (float4*)agg + (size_t)node * (D / 4);
#pragma unroll
        for (int v = 0; v < V; v++) ap[lane + v * 32] = a[v];
    }
}

// ---------------- gemm stage: C = relu(A1@W1^T + A2@W2^T + bias) ------------------
// 128x128 tiles, BK=16, f32x2 packed FMA, work-stealing tile scheduler.
#define N_MTILES ((N_NODES + 127) / 128)
template<int K>
__device__ void gemm_stage(const float* __restrict__ A1, const float* __restrict__ W1,
                           const float* __restrict__ A2, const float* __restrict__ W2,
                           const float* __restrict__ bias, float* __restrict__ C,
                           SmemGemm& sm, int* wq) {
    constexpr int BK = 16;
    constexpr int T = K / BK;
    int tid = threadIdx.x;
    int tx = tid & 15;
    int ty = tid >> 4;
    int lm = tid >> 2;
    int lk = (tid & 3) * 4;
    const float4 z4 = make_float4(0.f, 0.f, 0.f, 0.f);

    while (true) {
        if (tid == 0) sm.tile = atomicAdd(wq, 1);
        __syncthreads();
        int tile = sm.tile;
        if (tile >= N_MTILES * 2) break;
        int bm = (tile >> 1) * 128;
        int bn = (tile & 1) * 128;

        ull acc[8][4];
#pragma unroll
        for (int i = 0; i < 8; i++)
#pragma unroll
            for (int j = 0; j < 4; j++) acc[i][j] = pack2(0.f, 0.f);

#pragma unroll 1
        for (int phase = 0; phase < 2; phase++) {
            const float* A = phase ? A2 : A1;
            const float* W = phase ? W2 : W1;

            float4 ra0, ra1, rb0, rb1;
            {
                int r0 = bm + lm, r1 = bm + lm + 64;
                ra0 = (r0 < N_NODES) ? *(const float4*)(A + (size_t)r0 * K + lk) : z4;
                ra1 = (r1 < N_NODES) ? *(const float4*)(A + (size_t)r1 * K + lk) : z4;
                rb0 = *(const float4*)(W + (size_t)(bn + lm) * K + lk);
                rb1 = *(const float4*)(W + (size_t)(bn + lm + 64) * K + lk);
                sm.As[0][lk + 0][lm] = ra0.x; sm.As[0][lk + 1][lm] = ra0.y;
                sm.As[0][lk + 2][lm] = ra0.z; sm.As[0][lk + 3][lm] = ra0.w;
                sm.As[0][lk + 0][lm + 64] = ra1.x; sm.As[0][lk + 1][lm + 64] = ra1.y;
                sm.As[0][lk + 2][lm + 64] = ra1.z; sm.As[0][lk + 3][lm + 64] = ra1.w;
                sm.Bs[0][lk + 0][lm] = rb0.x; sm.Bs[0][lk + 1][lm] = rb0.y;
                sm.Bs[0][lk + 2][lm] = rb0.z; sm.Bs[0][lk + 3][lm] = rb0.w;
                sm.Bs[0][lk + 0][lm + 64] = rb1.x; sm.Bs[0][lk + 1][lm + 64] = rb1.y;
                sm.Bs[0][lk + 2][lm + 64] = rb1.z; sm.Bs[0][lk + 3][lm + 64] = rb1.w;
            }
            __syncthreads();

#pragma unroll 1
            for (int t = 0; t < T; t++) {
                int cur = t & 1, nxt = cur ^ 1;
                if (t + 1 < T) {
                    int k0 = (t + 1) * BK;
                    int r0 = bm + lm, r1 = bm + lm + 64;
                    ra0 = (r0 < N_NODES) ? *(const float4*)(A + (size_t)r0 * K + k0 + lk) : z4;
                    ra1 = (r1 < N_NODES) ? *(const float4*)(A + (size_t)r1 * K + k0 + lk) : z4;
                    rb0 = *(const float4*)(W + (size_t)(bn + lm) * K + k0 + lk);
                    rb1 = *(const float4*)(W + (size_t)(bn + lm + 64) * K + k0 + lk);
                }
#pragma unroll
                for (int k = 0; k < BK; k++) {
                    float4 av0 = *(const float4*)&sm.As[cur][k][ty * 8];
                    float4 av1 = *(const float4*)&sm.As[cur][k][ty * 8 + 4];
                    float4 bv0 = *(const float4*)&sm.Bs[cur][k][tx * 4];
                    float4 bv1 = *(const float4*)&sm.Bs[cur][k][64 + tx * 4];
                    ull b0 = pack2(bv0.x, bv0.y);
                    ull b1 = pack2(bv0.z, bv0.w);
                    ull b2 = pack2(bv1.x, bv1.y);
                    ull b3 = pack2(bv1.z, bv1.w);
                    ull ad;
                    ad = pack2(av0.x, av0.x);
                    acc[0][0] = fma2(ad, b0, acc[0][0]); acc[0][1] = fma2(ad, b1, acc[0][1]);
                    acc[0][2] = fma2(ad, b2, acc[0][2]); acc[0][3] = fma2(ad, b3, acc[0][3]);
                    ad = pack2(av0.y, av0.y);
                    acc[1][0] = fma2(ad, b0, acc[1][0]); acc[1][1] = fma2(ad, b1, acc[1][1]);
                    acc[1][2] = fma2(ad, b2, acc[1][2]); acc[1][3] = fma2(ad, b3, acc[1][3]);
                    ad = pack2(av0.z, av0.z);
                    acc[2][0] = fma2(ad, b0, acc[2][0]); acc[2][1] = fma2(ad, b1, acc[2][1]);
                    acc[2][2] = fma2(ad, b2, acc[2][2]); acc[2][3] = fma2(ad, b3, acc[2][3]);
                    ad = pack2(av0.w, av0.w);
                    acc[3][0] = fma2(ad, b0, acc[3][0]); acc[3][1] = fma2(ad, b1, acc[3][1]);
                    acc[3][2] = fma2(ad, b2, acc[3][2]); acc[3][3] = fma2(ad, b3, acc[3][3]);
                    ad = pack2(av1.x, av1.x);
                    acc[4][0] = fma2(ad, b0, acc[4][0]); acc[4][1] = fma2(ad, b1, acc[4][1]);
                    acc[4][2] = fma2(ad, b2, acc[4][2]); acc[4][3] = fma2(ad, b3, acc[4][3]);
                    ad = pack2(av1.y, av1.y);
                    acc[5][0] = fma2(ad, b0, acc[5][0]); acc[5][1] = fma2(ad, b1, acc[5][1]);
                    acc[5][2] = fma2(ad, b2, acc[5][2]); acc[5][3] = fma2(ad, b3, acc[5][3]);
                    ad = pack2(av1.z, av1.z);
                    acc[6][0] = fma2(ad, b0, acc[6][0]); acc[6][1] = fma2(ad, b1, acc[6][1]);
                    acc[6][2] = fma2(ad, b2, acc[6][2]); acc[6][3] = fma2(ad, b3, acc[6][3]);
                    ad = pack2(av1.w, av1.w);
                    acc[7][0] = fma2(ad, b0, acc[7][0]); acc[7][1] = fma2(ad, b1, acc[7][1]);
                    acc[7][2] = fma2(ad, b2, acc[7][2]); acc[7][3] = fma2(ad, b3, acc[7][3]);
                }
                if (t + 1 < T) {
                    sm.As[nxt][lk + 0][lm] = ra0.x; sm.As[nxt][lk + 1][lm] = ra0.y;
                    sm.As[nxt][lk + 2][lm] = ra0.z; sm.As[nxt][lk + 3][lm] = ra0.w;
                    sm.As[nxt][lk + 0][lm + 64] = ra1.x; sm.As[nxt][lk + 1][lm + 64] = ra1.y;
                    sm.As[nxt][lk + 2][lm + 64] = ra1.z; sm.As[nxt][lk + 3][lm + 64] = ra1.w;
                    sm.Bs[nxt][lk + 0][lm] = rb0.x; sm.Bs[nxt][lk + 1][lm] = rb0.y;
                    sm.Bs[nxt][lk + 2][lm] = rb0.z; sm.Bs[nxt][lk + 3][lm] = rb0.w;
                    sm.Bs[nxt][lk + 0][lm + 64] = rb1.x; sm.Bs[nxt][lk + 1][lm + 64] = rb1.y;
                    sm.Bs[nxt][lk + 2][lm + 64] = rb1.z; sm.Bs[nxt][lk + 3][lm + 64] = rb1.w;
                }
                __syncthreads();
            }
            __syncthreads();
        }

        // epilogue: bias + relu
        float4 bb0 = *(const float4*)(bias + bn + tx * 4);
        float4 bb1 = *(const float4*)(bias + bn + 64 + tx * 4);
#pragma unroll
        for (int i = 0; i < 8; i++) {
            int row = bm + ty * 8 + i;
            if (row < N_NODES) {
                float c0, c1, c2, c3, c4, c5, c6, c7;
                unpack2(acc[i][0], c0, c1);
                unpack2(acc[i][1], c2, c3);
                unpack2(acc[i][2], c4, c5);
                unpack2(acc[i][3], c6, c7);
                float4 o0 = make_float4(fmaxf(c0 + bb0.x, 0.f), fmaxf(c1 + bb0.y, 0.f),
                                        fmaxf(c2 + bb0.z, 0.f), fmaxf(c3 + bb0.w, 0.f));
                float4 o1 = make_float4(fmaxf(c4 + bb1.x, 0.f), fmaxf(c5 + bb1.y, 0.f),
                                        fmaxf(c6 + bb1.z, 0.f), fmaxf(c7 + bb1.w, 0.f));
                float* cp = C + (size_t)row * D_HID + bn + tx * 4;
                *(float4*)cp = o0;
                *(float4*)(cp + 64) = o1;
            }
        }
    }
}

// ---------------- the mega kernel ----------------
__global__ __launch_bounds__(NT, 2) void mega_kernel(
    const float* __restrict__ x, const void* __restrict__ ei, const void* __restrict__ bt,
    const float* __restrict__ W1_root, const float* __restrict__ W1_rel, const float* __restrict__ b1,
    const float* __restrict__ W2_root, const float* __restrict__ W2_rel, const float* __restrict__ b2,
    const float* __restrict__ Wfc, const float* __restrict__ bfc, float* __restrict__ out) {
    __shared__ SmemAll sm;
    const int b = blockIdx.x, t = threadIdx.x;
    const int nb = gridDim.x;
    int epoch = 0;

    const int i64 = g_idx64;   // set by reset_kernel

    // A: histogram of in-degrees (g_cnt zeroed by reset_kernel)
    for (int i = b * NT + t; i < N_EDGES; i += nb * NT) {
        int d = load_idx_(ei, i + N_EDGES, i64);
        atomicAdd(&g_cnt[d], 1);
    }
    gridbar(++epoch * nb);

    // B: exclusive scan -> g_row / g_cur
    {
        const int CHUNK = (N_NODES + nb - 1) / nb;
        int base = b * CHUNK;
        int lim = base + CHUNK; if (lim > N_NODES) lim = N_NODES;
        int i0 = base + t * 2, i1 = i0 + 1;
        int v0 = (i0 < lim) ? g_cnt[i0] : 0;
        int v1 = (i1 < lim) ? g_cnt[i1] : 0;
        int total;
        int ex = block_scan_excl(v0 + v1, sm.s, total);
        if (t == 0) g_bagg[b] = total;
        gridbar(++epoch * nb);
        if (b == 0) {
            int j0 = t * 2, j1 = j0 + 1;
            int w0 = (j0 < nb) ? g_bagg[j0] : 0;
            int w1 = (j1 < nb) ? g_bagg[j1] : 0;
            int btot;
            int bex = block_scan_excl(w0 + w1, sm.s, btot);
            if (j0 < nb) g_bpref[j0] = bex;
            if (j1 < nb) g_bpref[j1] = bex + w0;
        }
        gridbar(++epoch * nb);
        int off = g_bpref[b];
        if (i0 < lim) { int r = off + ex;      g_row[i0] = r; g_cur[i0] = r; }
        if (i1 < lim) { int r = off + ex + v0; g_row[i1] = r; g_cur[i1] = r; }
        if (b == 0 && t == 0) g_row[N_NODES] = N_EDGES;
    }
    gridbar(++epoch * nb);

    // C: CSR fill
    for (int i = b * NT + t; i < N_EDGES; i += nb * NT) {
        int s = load_idx_(ei, i, i64);
        int d = load_idx_(ei, i + N_EDGES, i64);
        g_col[atomicAdd(&g_cur[d], 1)] = s;
    }
    gridbar(++epoch * nb);

    // D: gather layer 1
    gather_stage<D_IN>(x, g_agg1);
    gridbar(++epoch * nb);

    // E: dual GEMM layer 1
    gemm_stage<D_IN>(x, W1_root, g_agg1, W1_rel, b1, g_h1, sm.g, &g_wq[0]);
    gridbar(++epoch * nb);

    // F: gather layer 2
    gather_stage<D_HID>(g_h1, g_agg2);
    gridbar(++epoch * nb);

    // G: dual GEMM layer 2
    gemm_stage<D_HID>(g_h1, W2_root, g_agg2, W2_rel, b2, g_h2, sm.g, &g_wq[1]);
    gridbar(++epoch * nb);

    // H: mean-pool + FC + sigmoid (batch sorted -> contiguous segments)
    for (int g = b; g < N_GRAPHS; g += nb) {
        __syncthreads();
        int start, end;
        {
            int lo = 0, hi = N_NODES;
            while (lo < hi) { int mid = (lo + hi) >> 1; if (load_idx_(bt, mid, i64) < g) lo = mid + 1; else hi = mid; }
            start = lo;
            lo = start; hi = N_NODES;
            while (lo < hi) { int mid = (lo + hi) >> 1; if (load_idx_(bt, mid, i64) < g + 1) lo = mid + 1; else hi = mid; }
            end = lo;
        }
        float s0 = 0.f, s1 = 0.f, s2 = 0.f, s3 = 0.f;
        int n = start;
        for (; n + 4 <= end; n += 4) {
            s0 += g_h2[(size_t)(n + 0) * D_HID + t];
            s1 += g_h2[(size_t)(n + 1) * D_HID + t];
            s2 += g_h2[(size_t)(n + 2) * D_HID + t];
            s3 += g_h2[(size_t)(n + 3) * D_HID + t];
        }
        for (; n < end; n++) s0 += g_h2[(size_t)n * D_HID + t];
        float s = (s0 + s1) + (s2 + s3);
        float p = s / fmaxf((float)(end - start), 1.0f);
        sm.p.r0[t] = p * Wfc[t];
        sm.p.r1[t] = p * Wfc[D_HID + t];
        __syncthreads();
        for (int off = 128; off > 0; off >>= 1) {
            if (t < off) { sm.p.r0[t] += sm.p.r0[t + off]; sm.p.r1[t] += sm.p.r1[t + off]; }
            __syncthreads();
        }
        if (t == 0) {
            out[g * 2 + 0] = 1.0f / (1.0f + expf(-(sm.p.r0[0] + bfc[0])));
            out[g * 2 + 1] = 1.0f / (1.0f + expf(-(sm.p.r1[0] + bfc[1])));
        }
    }
}

// ---------------- launch ----------------
extern "C" void kernel_launch(void* const* d_in, const int* in_sizes, int n_in,
                              void* d_out, int out_size) {
    const float* x  = (const float*)d_in[0];
    const void*  ei = d_in[1];
    const void*  bt = d_in[2];
    int wbase = (n_in >= 12 && in_sizes[3] == 1) ? 4 : 3;
    const float* W1_root = (const float*)d_in[wbase + 0];
    const float* W1_rel  = (const float*)d_in[wbase + 1];
    const float* b1      = (const float*)d_in[wbase + 2];
    const float* W2_root = (const float*)d_in[wbase + 3];
    const float* W2_rel  = (const float*)d_in[wbase + 4];
    const float* b2      = (const float*)d_in[wbase + 5];
    const float* Wfc     = (const float*)d_in[wbase + 6];
    const float* bfc     = (const float*)d_in[wbase + 7];
    float* out = (float*)d_out;

    // residency-safe grid sizing (deterministic host query; no allocation)
    int occ = 1;
    cudaOccupancyMaxActiveBlocksPerMultiprocessor(&occ, mega_kernel, NT, 0);
    if (occ < 1) occ = 1;
    if (occ > 2) occ = 2;
    int nb = 148 * occ;

    reset_kernel<<<256, 256>>>((const int*)ei);
    mega_kernel<<<nb, NT>>>(x, ei, bt, W1_root, W1_rel, b1,
                            W2_root, W2_rel, b2, Wfc, bfc, out);
    (void)out_size;
}